// round 2
// baseline (speedup 1.0000x reference)
#include <cuda_runtime.h>
#include <math.h>

// ---------------------------------------------------------------------------
// LSTM decoder: B=512, L=512, H=256, M=17, gates=1024, K_in=273 (=256 z + 17 out_prev)
//
// Phase 1 (parallel): Z[t][b][j] = sum_k z[b][t][k] * W_ih[j][17+k] + b_ih[j]+b_hh[j]
// Phase 2 (sequential, 512 graph nodes): per step t
//     gates = Z[t] + h_{t-1} @ W_hh^T + out_{t-1} @ W_ih[:, :17]^T
//     c_t = sig(f)*c + sig(i)*tanh(g);  h_t = sig(o)*tanh(c_t)
//     out_{t-1} = h_{t-1} @ W_lin^T + b_lin   (computed in-kernel, written to d_out)
// Phase 3: final projection writes out[511].
// ---------------------------------------------------------------------------

#define BATCH 512
#define SEQL  512
#define HID   256
#define MF    17
#define G4    1024
#define KIN   273
#define KPAD  274            // padded (even) K for packed f32x2

typedef unsigned long long ull;

// scratch (sanctioned __device__ globals; no allocation)
__device__ float g_Z[(size_t)SEQL * BATCH * G4];     // 1 GB
__device__ float g_hA[BATCH * HID];
__device__ float g_hB[BATCH * HID];
__device__ float g_cS[BATCH * HID];

__device__ __forceinline__ void ffma2(ull& d, ull a, ull b) {
    asm volatile("fma.rn.f32x2 %0, %1, %2, %0;" : "+l"(d) : "l"(a), "l"(b));
}
__device__ __forceinline__ float hsum2(ull u) {
    return __uint_as_float((unsigned)u) + __uint_as_float((unsigned)(u >> 32));
}
__device__ __forceinline__ float sigm(float x) { return 1.0f / (1.0f + __expf(-x)); }

// ---------------------------------------------------------------------------
// Phase 1: Z precompute GEMM. Rows R = t*512+b (262144), cols = 1024, K = 256.
// Tile 128x128, 512 threads, thread = 4 rows x 8 cols, packed f32x2 MACs.
// ---------------------------------------------------------------------------
__global__ __launch_bounds__(512, 1)
void precompute_z(const float* __restrict__ inseq, const float* __restrict__ Wih,
                  const float* __restrict__ bih,   const float* __restrict__ bhh) {
    __shared__ float As[128 * 20];   // stride 20: float4-aligned stores, broadcast reads
    __shared__ float Bs[128 * 18];   // stride 18: 2-way max conflict on LDS.64

    const int tid = threadIdx.x;
    const int Rt  = blockIdx.x * 128;
    const int Ct  = blockIdx.y * 128;
    const int ty  = tid >> 4;        // 0..31
    const int tx  = tid & 15;        // 0..15

    ull acc[4][8];
#pragma unroll
    for (int j = 0; j < 4; j++)
#pragma unroll
        for (int i = 0; i < 8; i++) acc[j][i] = 0ull;

    const int arr = tid >> 2;              // A-load row 0..127
    const int akk = (tid & 3) * 4;         // A-load k offset (float4)
    {
        // precompute A source base for this row
    }
    const int Ra = Rt + arr;
    const int ab = Ra & 511;               // batch
    const int at = Ra >> 9;                // time
    const float* aSrc = inseq + ((size_t)(ab * SEQL + at)) * HID;

    for (int k0 = 0; k0 < HID; k0 += 16) {
        // load A tile (128 x 16) as float4s
        float4 av = *reinterpret_cast<const float4*>(aSrc + k0 + akk);
        *reinterpret_cast<float4*>(&As[arr * 20 + akk]) = av;
        // load B tile (128 cols x 16 k), scalar (stride-273 source)
#pragma unroll
        for (int p = 0; p < 4; p++) {
            int idx = tid + p * 512;
            int c = idx >> 4, kk = idx & 15;
            Bs[c * 18 + kk] = Wih[(size_t)(Ct + c) * KIN + 17 + k0 + kk];
        }
        __syncthreads();
#pragma unroll
        for (int kp = 0; kp < 8; kp++) {
            ull a[4], b[8];
#pragma unroll
            for (int j = 0; j < 4; j++)
                a[j] = *reinterpret_cast<const ull*>(&As[(ty + 32 * j) * 20 + 2 * kp]);
#pragma unroll
            for (int i = 0; i < 8; i++)
                b[i] = *reinterpret_cast<const ull*>(&Bs[(tx + 16 * i) * 18 + 2 * kp]);
#pragma unroll
            for (int j = 0; j < 4; j++)
#pragma unroll
                for (int i = 0; i < 8; i++) ffma2(acc[j][i], a[j], b[i]);
        }
        __syncthreads();
    }

#pragma unroll
    for (int j = 0; j < 4; j++) {
        int r = Rt + ty + 32 * j;
        float* zr = g_Z + (size_t)r * G4;
#pragma unroll
        for (int i = 0; i < 8; i++) {
            int c = Ct + tx + 16 * i;
            zr[c] = hsum2(acc[j][i]) + bih[c] + bhh[c];
        }
    }
}

// ---------------------------------------------------------------------------
// Phase 2: one step. Grid (16 batch-tiles of 32, 16 dim-tiles of 16), 256 thr.
// SMEM: xs[32][274] = [h | out_prev | pad], Ws[64][274] = W_hh|W_ih[:,0:17]|pad
// Thread: 2 batch rows x (i,f,g,o of one hidden dim).
// ---------------------------------------------------------------------------
#define SMEM_STEP ((32 * KPAD + 64 * KPAD) * 4)

__global__ __launch_bounds__(256, 2)
void lstm_step(int t,
               const float* __restrict__ h0,  const float* __restrict__ c0,
               const float* __restrict__ Whh, const float* __restrict__ Wih,
               const float* __restrict__ Wlin, const float* __restrict__ blin,
               float* __restrict__ out) {
    extern __shared__ float sm[];
    float* xs = sm;                 // 32 * 274
    float* Ws = sm + 32 * KPAD;     // 64 * 274

    const int tid = threadIdx.x;
    const int b0  = blockIdx.x * 32;
    const int d0  = blockIdx.y * 16;

    const float* h_in  = (t == 0) ? h0 : ((t & 1) ? g_hA : g_hB);
    float*       h_out = (t & 1) ? g_hB : g_hA;

    // phase 1: stage x (h part; out_prev slots zeroed) and W slice
    for (int idx = tid; idx < 32 * KPAD; idx += 256) {
        int bl = idx / KPAD, k = idx - bl * KPAD;
        xs[idx] = (k < HID) ? h_in[(b0 + bl) * HID + k] : 0.0f;
    }
    for (int idx = tid; idx < 64 * KPAD; idx += 256) {
        int lr = idx / KPAD, k = idx - lr * KPAD;
        int j  = (lr >> 4) * HID + d0 + (lr & 15);   // gate*256 + dim
        float v;
        if (k < HID)      v = Whh[(size_t)j * HID + k];
        else if (k < KIN) v = Wih[(size_t)j * KIN + (k - HID)];
        else              v = 0.0f;
        Ws[idx] = v;
    }
    __syncthreads();

    // phase 2: out_prev = h_in @ W_lin^T + b_lin (also IS output row t-1)
    if (t > 0) {
        for (int idx = tid; idx < 32 * MF; idx += 256) {
            int bl = idx / MF, m = idx - bl * MF;
            const float* wl = Wlin + m * HID;
            const float* xr = xs + bl * KPAD;
            float s = blin[m];
#pragma unroll 8
            for (int k = 0; k < HID; k++) s += xr[k] * wl[k];
            xs[bl * KPAD + HID + m] = s;
            if (blockIdx.y == 0)
                out[((size_t)(b0 + bl) * SEQL + (t - 1)) * MF + m] = s;
        }
    }
    __syncthreads();

    // phase 3: gates GEMM with packed f32x2
    const int di = tid >> 4;             // hidden dim within tile, 0..15
    const int bq = (tid & 15) * 2;       // batch pair

    const ull* x0 = reinterpret_cast<const ull*>(xs + bq * KPAD);
    const ull* x1 = reinterpret_cast<const ull*>(xs + (bq + 1) * KPAD);
    const ull* w0 = reinterpret_cast<const ull*>(Ws + (di)      * KPAD);  // i
    const ull* w1 = reinterpret_cast<const ull*>(Ws + (16 + di) * KPAD);  // f
    const ull* w2 = reinterpret_cast<const ull*>(Ws + (32 + di) * KPAD);  // g
    const ull* w3 = reinterpret_cast<const ull*>(Ws + (48 + di) * KPAD);  // o

    ull acc[2][4];
#pragma unroll
    for (int b = 0; b < 2; b++)
#pragma unroll
        for (int g = 0; g < 4; g++) acc[b][g] = 0ull;

#pragma unroll 4
    for (int kp = 0; kp < KPAD / 2; kp++) {
        ull xa = x0[kp], xb = x1[kp];
        ull wa = w0[kp], wb = w1[kp], wc = w2[kp], wd = w3[kp];
        ffma2(acc[0][0], xa, wa); ffma2(acc[1][0], xb, wa);
        ffma2(acc[0][1], xa, wb); ffma2(acc[1][1], xb, wb);
        ffma2(acc[0][2], xa, wc); ffma2(acc[1][2], xb, wc);
        ffma2(acc[0][3], xa, wd); ffma2(acc[1][3], xb, wd);
    }

    const int d = d0 + di;
#pragma unroll
    for (int bl = 0; bl < 2; bl++) {
        int b = b0 + bq + bl;
        const float* zr = g_Z + ((size_t)t * BATCH + b) * G4;
        float iv = hsum2(acc[bl][0]) + zr[d];
        float fv = hsum2(acc[bl][1]) + zr[HID + d];
        float gv = hsum2(acc[bl][2]) + zr[2 * HID + d];
        float ov = hsum2(acc[bl][3]) + zr[3 * HID + d];
        int idx = b * HID + d;
        float cold = (t == 0) ? c0[idx] : g_cS[idx];
        float cn = sigm(fv) * cold + sigm(iv) * tanhf(gv);
        float hn = sigm(ov) * tanhf(cn);
        g_cS[idx]  = cn;
        h_out[idx] = hn;
    }
}

// ---------------------------------------------------------------------------
// Phase 3: out[:, 511, :] = h_511 @ W_lin^T + b_lin. h after step 511 = g_hB.
// ---------------------------------------------------------------------------
__global__ void final_proj(const float* __restrict__ Wlin,
                           const float* __restrict__ blin,
                           float* __restrict__ out) {
    __shared__ float hs[16 * HID];
    const int tid = threadIdx.x;      // 272 threads
    const int b0  = blockIdx.x * 16;
    for (int idx = tid; idx < 16 * HID; idx += 272)
        hs[idx] = g_hB[b0 * HID + idx];
    __syncthreads();
    int bl = tid / MF, m = tid - bl * MF;
    const float* wl = Wlin + m * HID;
    const float* xr = hs + bl * HID;
    float s = blin[m];
#pragma unroll 8
    for (int k = 0; k < HID; k++) s += xr[k] * wl[k];
    out[((size_t)(b0 + bl) * SEQL + (SEQL - 1)) * MF + m] = s;
}

// ---------------------------------------------------------------------------
extern "C" void kernel_launch(void* const* d_in, const int* in_sizes, int n_in,
                              void* d_out, int out_size) {
    const float* inseq = (const float*)d_in[0];
    const float* h0    = (const float*)d_in[1];
    const float* c0    = (const float*)d_in[2];
    const float* Wih   = (const float*)d_in[3];
    const float* Whh   = (const float*)d_in[4];
    const float* bih   = (const float*)d_in[5];
    const float* bhh   = (const float*)d_in[6];
    const float* Wlin  = (const float*)d_in[7];
    const float* blin  = (const float*)d_in[8];
    float* out = (float*)d_out;

    cudaFuncSetAttribute(lstm_step, cudaFuncAttributeMaxDynamicSharedMemorySize,
                         SMEM_STEP);

    // Phase 1: Z precompute (262144 x 1024, K=256)
    precompute_z<<<dim3(2048, 8), 512>>>(inseq, Wih, bih, bhh);

    // Phase 2: 512 sequential steps (stream order = dependency)
    for (int t = 0; t < SEQL; t++)
        lstm_step<<<dim3(16, 16), 256, SMEM_STEP>>>(t, h0, c0, Whh, Wih,
                                                    Wlin, blin, out);

    // Phase 3: last output row
    final_proj<<<32, 272>>>(Wlin, blin, out);
}

// round 3
// speedup vs baseline: 5.3836x; 5.3836x over previous
#include <cuda_runtime.h>
#include <math.h>

// ---------------------------------------------------------------------------
// LSTM decoder, persistent-kernel formulation.
//   Setup:   Wc = W_hh + W_ih[:, :17] @ W_lin   (1024x256), corr = W_ih[:, :17]@b_lin
//   Phase 1: Z[t][b][j] = z_t[b] . W_ih[j][17:] + b_ih[j] + b_hh[j]   (big GEMM)
//   Phase 2: ONE persistent kernel, 128 co-resident CTAs, 512 steps:
//              gates = Z[t] + h_{t-1} @ Wc^T (+corr, t>=1);  c in registers;
//              h history written to gmem; per-batch-tile counter barrier.
//   Phase 3: out[b][t][:] = h_hist[t][b] @ W_lin^T + b_lin   (parallel GEMM)
// ---------------------------------------------------------------------------

#define BATCH 512
#define SEQL  512
#define HID   256
#define MF    17
#define G4    1024
#define KIN   273

#define NBT   8      // batch tiles
#define BT    64     // batch rows per tile
#define NDT   16     // dim tiles
#define DT    16     // dims per tile
#define XSTR  258    // smem row stride in floats (258 mod 32 == 2 -> conflict-free)

typedef unsigned long long ull;

// scratch (__device__ globals; no allocation)
__device__ float g_Z[(size_t)SEQL * BATCH * G4];       // 1 GB
__device__ float g_hist[(size_t)SEQL * BATCH * HID];   // 256 MB
__device__ float g_Wc[G4 * HID];
__device__ float g_corr[G4];
__device__ int   g_cnt[NBT];

__device__ __forceinline__ void ffma2(ull& d, ull a, ull b) {
    asm volatile("fma.rn.f32x2 %0, %1, %2, %0;" : "+l"(d) : "l"(a), "l"(b));
}
__device__ __forceinline__ float hsum2(ull u) {
    return __uint_as_float((unsigned)u) + __uint_as_float((unsigned)(u >> 32));
}
__device__ __forceinline__ float sigm(float x) {
    return __fdividef(1.0f, 1.0f + __expf(-x));
}
__device__ __forceinline__ float tanh_e(float x) {
    return 1.0f - __fdividef(2.0f, __expf(2.0f * x) + 1.0f);
}

// ---------------------------------------------------------------------------
// Setup: Wc, corr, barrier-counter reset.  grid=1024 blocks x 256 thr.
// ---------------------------------------------------------------------------
__global__ void setup_fold(const float* __restrict__ Whh, const float* __restrict__ Wih,
                           const float* __restrict__ Wlin, const float* __restrict__ blin) {
    const int j = blockIdx.x;      // gate row 0..1023
    const int k = threadIdx.x;     // 0..255
    float s = Whh[j * HID + k];
#pragma unroll
    for (int m = 0; m < MF; m++)
        s += Wih[j * KIN + m] * Wlin[m * HID + k];
    g_Wc[j * HID + k] = s;
    if (k == 0) {
        float c = 0.0f;
#pragma unroll
        for (int m = 0; m < MF; m++) c += Wih[j * KIN + m] * blin[m];
        g_corr[j] = c;
    }
    if (j == 0 && k < NBT) g_cnt[k] = 0;
}

// ---------------------------------------------------------------------------
// Phase 1: Z precompute GEMM (unchanged from R2; fma-bound).
// ---------------------------------------------------------------------------
__global__ __launch_bounds__(512, 1)
void precompute_z(const float* __restrict__ inseq, const float* __restrict__ Wih,
                  const float* __restrict__ bih,   const float* __restrict__ bhh) {
    __shared__ float As[128 * 20];
    __shared__ float Bs[128 * 18];

    const int tid = threadIdx.x;
    const int Rt  = blockIdx.x * 128;
    const int Ct  = blockIdx.y * 128;
    const int ty  = tid >> 4;
    const int tx  = tid & 15;

    ull acc[4][8];
#pragma unroll
    for (int j = 0; j < 4; j++)
#pragma unroll
        for (int i = 0; i < 8; i++) acc[j][i] = 0ull;

    const int arr = tid >> 2;
    const int akk = (tid & 3) * 4;
    const int Ra  = Rt + arr;
    const int ab  = Ra & 511;
    const int at  = Ra >> 9;
    const float* aSrc = inseq + ((size_t)(ab * SEQL + at)) * HID;

    for (int k0 = 0; k0 < HID; k0 += 16) {
        float4 av = *reinterpret_cast<const float4*>(aSrc + k0 + akk);
        *reinterpret_cast<float4*>(&As[arr * 20 + akk]) = av;
#pragma unroll
        for (int p = 0; p < 4; p++) {
            int idx = tid + p * 512;
            int c = idx >> 4, kk = idx & 15;
            Bs[c * 18 + kk] = Wih[(size_t)(Ct + c) * KIN + 17 + k0 + kk];
        }
        __syncthreads();
#pragma unroll
        for (int kp = 0; kp < 8; kp++) {
            ull a[4], b[8];
#pragma unroll
            for (int j = 0; j < 4; j++)
                a[j] = *reinterpret_cast<const ull*>(&As[(ty + 32 * j) * 20 + 2 * kp]);
#pragma unroll
            for (int i = 0; i < 8; i++)
                b[i] = *reinterpret_cast<const ull*>(&Bs[(tx + 16 * i) * 18 + 2 * kp]);
#pragma unroll
            for (int j = 0; j < 4; j++)
#pragma unroll
                for (int i = 0; i < 8; i++) ffma2(acc[j][i], a[j], b[i]);
        }
        __syncthreads();
    }

#pragma unroll
    for (int j = 0; j < 4; j++) {
        int r = Rt + ty + 32 * j;
        float* zr = g_Z + (size_t)r * G4;
#pragma unroll
        for (int i = 0; i < 8; i++) {
            int c = Ct + tx + 16 * i;
            zr[c] = hsum2(acc[j][i]) + bih[c] + bhh[c];
        }
    }
}

// ---------------------------------------------------------------------------
// Phase 2: persistent recurrence. 128 CTAs (8 bt x 16 dt), 256 threads.
// Thread = 4 batch rows x 1 dim x 4 gates. c-state in registers.
// ---------------------------------------------------------------------------
#define SMEM_P (2 * BT * XSTR * 4)

__global__ __launch_bounds__(256, 1)
void lstm_persistent(const float* __restrict__ h0, const float* __restrict__ c0,
                     const float* __restrict__ Whh) {
    extern __shared__ float sm[];
    float* xs = sm;                // 64 x 258 (x rows)
    float* Ws = sm + BT * XSTR;    // 64 x 258 (rows = gate*16 + local dim)

    const int tid = threadIdx.x;
    const int bt  = blockIdx.x >> 4;
    const int dt  = blockIdx.x & 15;
    const int b0  = bt * BT;
    const int d0  = dt * DT;
    const int di  = tid & 15;
    const int bg  = tid >> 4;          // 0..15
    const int rb  = bg * 4;            // first of this thread's 4 batch rows
    const int d   = d0 + di;

    float c[4], corr4[4];
#pragma unroll
    for (int r = 0; r < 4; r++) c[r] = c0[(b0 + rb + r) * HID + d];
#pragma unroll
    for (int g = 0; g < 4; g++) corr4[g] = g_corr[g * HID + d];

    // stage W_hh (step 0 uses raw W_hh; Wc from step 1)
    for (int idx = tid; idx < BT * 128; idx += 256) {
        int lr = idx >> 7, p = idx & 127;
        int j  = (lr >> 4) * HID + d0 + (lr & 15);
        *reinterpret_cast<float2*>(&Ws[lr * XSTR + 2 * p]) =
            *reinterpret_cast<const float2*>(&Whh[(size_t)j * HID + 2 * p]);
    }

    for (int t = 0; t < SEQL; t++) {
        // ---- barrier: wait until all 16 dt-CTAs of this bt published h_{t-1}
        if (t > 0) {
            if (tid == 0) {
                volatile int* p = &g_cnt[bt];
                const int target = 16 * t;
                while (*p < target) { }
            }
            __syncthreads();
        }

        // ---- stage x = h_{t-1} (or h0)
        {
            const float* src = (t == 0) ? (h0 + (size_t)b0 * HID)
                                        : (g_hist + ((size_t)(t - 1) * BATCH + b0) * HID);
            for (int idx = tid; idx < BT * 128; idx += 256) {
                int lr = idx >> 7, p = idx & 127;
                float2 v = __ldcg(reinterpret_cast<const float2*>(src + lr * HID + 2 * p));
                *reinterpret_cast<float2*>(&xs[lr * XSTR + 2 * p]) = v;
            }
            if (t == 1) {  // swap in folded weights Wc (step-0 reads completed)
                for (int idx = tid; idx < BT * 128; idx += 256) {
                    int lr = idx >> 7, p = idx & 127;
                    int j  = (lr >> 4) * HID + d0 + (lr & 15);
                    *reinterpret_cast<float2*>(&Ws[lr * XSTR + 2 * p]) =
                        *reinterpret_cast<const float2*>(&g_Wc[(size_t)j * HID + 2 * p]);
                }
            }
        }

        // ---- Z prefetch into registers (DRAM latency hidden under GEMM issue)
        float z[4][4];
        {
            const float* zb = g_Z + ((size_t)t * BATCH + b0 + rb) * G4 + d;
#pragma unroll
            for (int r = 0; r < 4; r++)
#pragma unroll
                for (int g = 0; g < 4; g++)
                    z[r][g] = __ldcg(zb + r * G4 + g * HID);
        }
        __syncthreads();

        // ---- gates GEMM: 4 rows x 4 gates, K = 256 (128 f32x2 pairs)
        ull a00=0,a01=0,a02=0,a03=0, a10=0,a11=0,a12=0,a13=0;
        ull a20=0,a21=0,a22=0,a23=0, a30=0,a31=0,a32=0,a33=0;
        const ull* xp0 = reinterpret_cast<const ull*>(xs + (rb + 0) * XSTR);
        const ull* xp1 = reinterpret_cast<const ull*>(xs + (rb + 1) * XSTR);
        const ull* xp2 = reinterpret_cast<const ull*>(xs + (rb + 2) * XSTR);
        const ull* xp3 = reinterpret_cast<const ull*>(xs + (rb + 3) * XSTR);
        const ull* wp0 = reinterpret_cast<const ull*>(Ws + (0  + di) * XSTR);
        const ull* wp1 = reinterpret_cast<const ull*>(Ws + (16 + di) * XSTR);
        const ull* wp2 = reinterpret_cast<const ull*>(Ws + (32 + di) * XSTR);
        const ull* wp3 = reinterpret_cast<const ull*>(Ws + (48 + di) * XSTR);

        for (int k0 = 0; k0 < 128; k0 += 16) {
#pragma unroll
            for (int u = 0; u < 16; u++) {
                const int k = k0 + u;
                ull x0 = xp0[k], x1 = xp1[k], x2 = xp2[k], x3 = xp3[k];
                ull w0 = wp0[k], w1 = wp1[k], w2 = wp2[k], w3 = wp3[k];
                ffma2(a00, x0, w0); ffma2(a01, x0, w1); ffma2(a02, x0, w2); ffma2(a03, x0, w3);
                ffma2(a10, x1, w0); ffma2(a11, x1, w1); ffma2(a12, x1, w2); ffma2(a13, x1, w3);
                ffma2(a20, x2, w0); ffma2(a21, x2, w1); ffma2(a22, x2, w2); ffma2(a23, x2, w3);
                ffma2(a30, x3, w0); ffma2(a31, x3, w1); ffma2(a32, x3, w2); ffma2(a33, x3, w3);
            }
        }

        // ---- epilogue: activations, c update (registers), publish h
        ull accs[4][4] = {{a00,a01,a02,a03},{a10,a11,a12,a13},
                          {a20,a21,a22,a23},{a30,a31,a32,a33}};
#pragma unroll
        for (int r = 0; r < 4; r++) {
            float iv = hsum2(accs[r][0]) + z[r][0];
            float fv = hsum2(accs[r][1]) + z[r][1];
            float gv = hsum2(accs[r][2]) + z[r][2];
            float ov = hsum2(accs[r][3]) + z[r][3];
            if (t > 0) { iv += corr4[0]; fv += corr4[1]; gv += corr4[2]; ov += corr4[3]; }
            float cn = sigm(fv) * c[r] + sigm(iv) * tanh_e(gv);
            c[r] = cn;
            float hn = sigm(ov) * tanh_e(cn);
            g_hist[((size_t)t * BATCH + b0 + rb + r) * HID + d] = hn;
        }
        __threadfence();
        __syncthreads();
        if (tid == 0) atomicAdd(&g_cnt[bt], 1);
    }
}

// ---------------------------------------------------------------------------
// Phase 3: out[b][t][m] = h_hist[t][b] . W_lin[m] + b_lin[m].
// grid (512 t, 32 b-tiles), 272 threads = 16 rows x 17 outputs.
// ---------------------------------------------------------------------------
__global__ void out_proj(const float* __restrict__ Wlin, const float* __restrict__ blin,
                         float* __restrict__ out) {
    __shared__ float hs[16 * HID];
    const int t  = blockIdx.x;
    const int b0 = blockIdx.y * 16;
    const float* src = g_hist + ((size_t)t * BATCH + b0) * HID;
    for (int idx = threadIdx.x; idx < 16 * HID / 2; idx += 272)
        *reinterpret_cast<float2*>(&hs[2 * idx]) =
            *reinterpret_cast<const float2*>(&src[2 * idx]);
    __syncthreads();

    const int bl = threadIdx.x / MF;
    const int m  = threadIdx.x - bl * MF;
    const ull* xr = reinterpret_cast<const ull*>(hs + bl * HID);
    const ull* wl = reinterpret_cast<const ull*>(Wlin + m * HID);
    ull q0 = 0, q1 = 0, q2 = 0, q3 = 0;
#pragma unroll 8
    for (int k = 0; k < 128; k += 4) {
        ffma2(q0, xr[k],     wl[k]);
        ffma2(q1, xr[k + 1], wl[k + 1]);
        ffma2(q2, xr[k + 2], wl[k + 2]);
        ffma2(q3, xr[k + 3], wl[k + 3]);
    }
    float s = blin[m] + hsum2(q0) + hsum2(q1) + hsum2(q2) + hsum2(q3);
    out[((size_t)(b0 + bl) * SEQL + t) * MF + m] = s;
}

// ---------------------------------------------------------------------------
extern "C" void kernel_launch(void* const* d_in, const int* in_sizes, int n_in,
                              void* d_out, int out_size) {
    const float* inseq = (const float*)d_in[0];
    const float* h0    = (const float*)d_in[1];
    const float* c0    = (const float*)d_in[2];
    const float* Wih   = (const float*)d_in[3];
    const float* Whh   = (const float*)d_in[4];
    const float* bih   = (const float*)d_in[5];
    const float* bhh   = (const float*)d_in[6];
    const float* Wlin  = (const float*)d_in[7];
    const float* blin  = (const float*)d_in[8];
    float* out = (float*)d_out;

    cudaFuncSetAttribute(lstm_persistent, cudaFuncAttributeMaxDynamicSharedMemorySize,
                         SMEM_P);

    // setup: folded weights + barrier counters (reset every call -> replayable)
    setup_fold<<<G4, HID>>>(Whh, Wih, Wlin, blin);

    // phase 1: Z precompute
    precompute_z<<<dim3(2048, 8), 512>>>(inseq, Wih, bih, bhh);

    // phase 2: persistent recurrence (all 512 steps in one kernel)
    lstm_persistent<<<NBT * NDT, 256, SMEM_P>>>(h0, c0, Whh);

    // phase 3: all outputs
    out_proj<<<dim3(SEQL, 32), 272>>>(Wlin, blin, out);
}

// round 6
// speedup vs baseline: 5.5100x; 1.0235x over previous
#include <cuda_runtime.h>
#include <cstdint>
#include <math.h>

// ---------------------------------------------------------------------------
// LSTM decoder (SIMT-only: harness compiles via compute_103 -> no tcgen05).
//  setup:    Wc = W_hh + W_ih[:,:17]@W_lin (1024x256), corr = W_ih[:,:17]@b_lin
//  phase 1:  Z[t][b] = z . W_ih[:,17:]^T + b_ih + b_hh   (FFMA2 tiled GEMM)
//  phase 2:  ONE persistent kernel, 128 CTAs, 512 steps:
//              gates = Z[t] + h@Wc^T (+corr, t>0); c in registers;
//              h history to gmem; per-batch-tile counter barrier.
//  phase 3:  out[b][t] = hist[t][b]@W_lin^T + b_lin
// ---------------------------------------------------------------------------

#define BATCH 512
#define SEQL  512
#define HID   256
#define MF    17
#define G4    1024
#define KIN   273

#define NBT   8
#define BT    64
#define NDT   16
#define DT    16
#define XSTR  260        // floats; multiple of 4 (16B aligned rows); mod 32 == 4

typedef unsigned long long ull;

// __device__ scratch (no allocation)
__device__ float g_Z[(size_t)SEQL * BATCH * G4];     // 1 GB
__device__ float g_hist[(size_t)SEQL * BATCH * HID]; // 256 MB
__device__ float g_Wc[G4 * HID];
__device__ float g_corr[G4];
__device__ int   g_cnt[NBT];

__device__ __forceinline__ void ffma2(ull& d, ull a, ull b) {
    asm volatile("fma.rn.f32x2 %0, %1, %2, %0;" : "+l"(d) : "l"(a), "l"(b));
}
__device__ __forceinline__ float hsum2(ull u) {
    return __uint_as_float((unsigned)u) + __uint_as_float((unsigned)(u >> 32));
}
__device__ __forceinline__ float sigm(float x) {
    return __fdividef(1.0f, 1.0f + __expf(-x));
}
__device__ __forceinline__ float tanh_e(float x) {
    return 1.0f - __fdividef(2.0f, __expf(2.0f * x) + 1.0f);
}

// ---------------------------------------------------------------------------
// setup: Wc, corr, counter reset
// ---------------------------------------------------------------------------
__global__ void setup_fold(const float* __restrict__ Whh, const float* __restrict__ Wih,
                           const float* __restrict__ Wlin, const float* __restrict__ blin) {
    const int j = blockIdx.x;      // 0..1023
    const int k = threadIdx.x;     // 0..255
    float s = Whh[j * HID + k];
#pragma unroll
    for (int m = 0; m < MF; m++)
        s += Wih[j * KIN + m] * Wlin[m * HID + k];
    g_Wc[j * HID + k] = s;
    if (k == 0) {
        float c = 0.0f;
#pragma unroll
        for (int m = 0; m < MF; m++) c += Wih[j * KIN + m] * blin[m];
        g_corr[j] = c;
    }
    if (j == 0 && k < NBT) g_cnt[k] = 0;
}

// ---------------------------------------------------------------------------
// Phase 1: Z precompute GEMM (262144 x 1024, K=256). Proven R2 kernel.
// ---------------------------------------------------------------------------
__global__ __launch_bounds__(512, 1)
void precompute_z(const float* __restrict__ inseq, const float* __restrict__ Wih,
                  const float* __restrict__ bih,   const float* __restrict__ bhh) {
    __shared__ float As[128 * 20];
    __shared__ float Bs[128 * 18];

    const int tid = threadIdx.x;
    const int Rt  = blockIdx.x * 128;
    const int Ct  = blockIdx.y * 128;
    const int ty  = tid >> 4;
    const int tx  = tid & 15;

    ull acc[4][8];
#pragma unroll
    for (int j = 0; j < 4; j++)
#pragma unroll
        for (int i = 0; i < 8; i++) acc[j][i] = 0ull;

    const int arr = tid >> 2;
    const int akk = (tid & 3) * 4;
    const int Ra  = Rt + arr;
    const int ab  = Ra & 511;
    const int at  = Ra >> 9;
    const float* aSrc = inseq + ((size_t)(ab * SEQL + at)) * HID;

    for (int k0 = 0; k0 < HID; k0 += 16) {
        float4 av = *reinterpret_cast<const float4*>(aSrc + k0 + akk);
        *reinterpret_cast<float4*>(&As[arr * 20 + akk]) = av;
#pragma unroll
        for (int p = 0; p < 4; p++) {
            int idx = tid + p * 512;
            int c = idx >> 4, kk = idx & 15;
            Bs[c * 18 + kk] = Wih[(size_t)(Ct + c) * KIN + 17 + k0 + kk];
        }
        __syncthreads();
#pragma unroll
        for (int kp = 0; kp < 8; kp++) {
            ull a[4], b[8];
#pragma unroll
            for (int j = 0; j < 4; j++)
                a[j] = *reinterpret_cast<const ull*>(&As[(ty + 32 * j) * 20 + 2 * kp]);
#pragma unroll
            for (int i = 0; i < 8; i++)
                b[i] = *reinterpret_cast<const ull*>(&Bs[(tx + 16 * i) * 18 + 2 * kp]);
#pragma unroll
            for (int j = 0; j < 4; j++)
#pragma unroll
                for (int i = 0; i < 8; i++) ffma2(acc[j][i], a[j], b[i]);
        }
        __syncthreads();
    }

#pragma unroll
    for (int j = 0; j < 4; j++) {
        int r = Rt + ty + 32 * j;
        float* zr = g_Z + (size_t)r * G4;
#pragma unroll
        for (int i = 0; i < 8; i++) {
            int c = Ct + tx + 16 * i;
            zr[c] = hsum2(acc[j][i]) + bih[c] + bhh[c];
        }
    }
}

// ---------------------------------------------------------------------------
// Phase 2: persistent recurrence. 128 CTAs (8 bt x 16 dt), 256 threads.
// Thread = 4 batch rows x 1 dim x 4 gates; c-state in registers.
// ---------------------------------------------------------------------------
#define SMEM_P (2 * BT * XSTR * 4)

__global__ __launch_bounds__(256, 1)
void lstm_persistent(const float* __restrict__ h0, const float* __restrict__ c0,
                     const float* __restrict__ Whh) {
    extern __shared__ float smf[];
    float* xs = smf;                 // 64 x 260
    float* Ws = smf + BT * XSTR;     // 64 x 260

    const int tid = threadIdx.x;
    const int bt  = blockIdx.x >> 4;
    const int dt  = blockIdx.x & 15;
    const int b0  = bt * BT;
    const int d0  = dt * DT;
    const int di  = tid & 15;
    const int bg  = tid >> 4;
    const int rb  = bg * 4;
    const int d   = d0 + di;

    float c[4], corr4[4];
#pragma unroll
    for (int r = 0; r < 4; r++) c[r] = c0[(b0 + rb + r) * HID + d];
#pragma unroll
    for (int g = 0; g < 4; g++) corr4[g] = g_corr[g * HID + d];

    // stage raw W_hh for step 0 (Wc from step 1)
    for (int idx = tid; idx < BT * 64; idx += 256) {
        int lr = idx >> 6, p = idx & 63;
        int j  = (lr >> 4) * HID + d0 + (lr & 15);
        *reinterpret_cast<float4*>(&Ws[lr * XSTR + 4 * p]) =
            *reinterpret_cast<const float4*>(&Whh[(size_t)j * HID + 4 * p]);
    }

    for (int t = 0; t < SEQL; t++) {
        // Z prefetch: h-independent -> issue before barrier spin
        float z[4][4];
        {
            const float* zb = g_Z + ((size_t)t * BATCH + b0 + rb) * G4 + d;
#pragma unroll
            for (int r = 0; r < 4; r++)
#pragma unroll
                for (int g = 0; g < 4; g++)
                    z[r][g] = __ldcg(zb + r * G4 + g * HID);
        }

        if (t > 0) {
            if (tid == 0) {
                volatile int* p = &g_cnt[bt];
                const int target = 16 * t;
                while (*p < target) { }
            }
            __syncthreads();
        }

        // stage x = h_{t-1} (float4)
        {
            const float* src = (t == 0) ? (h0 + (size_t)b0 * HID)
                                        : (g_hist + ((size_t)(t - 1) * BATCH + b0) * HID);
            for (int idx = tid; idx < BT * 64; idx += 256) {
                int lr = idx >> 6, p = idx & 63;
                float4 v = __ldcg(reinterpret_cast<const float4*>(src + lr * HID + 4 * p));
                *reinterpret_cast<float4*>(&xs[lr * XSTR + 4 * p]) = v;
            }
        }
        __syncthreads();

        // gates GEMM: 4 rows x 4 gates, K=256 as 64 float4 quads (LDS.128)
        ull a00=0,a01=0,a02=0,a03=0, a10=0,a11=0,a12=0,a13=0;
        ull a20=0,a21=0,a22=0,a23=0, a30=0,a31=0,a32=0,a33=0;
        const ulonglong2* xp0 = reinterpret_cast<const ulonglong2*>(xs + (rb + 0) * XSTR);
        const ulonglong2* xp1 = reinterpret_cast<const ulonglong2*>(xs + (rb + 1) * XSTR);
        const ulonglong2* xp2 = reinterpret_cast<const ulonglong2*>(xs + (rb + 2) * XSTR);
        const ulonglong2* xp3 = reinterpret_cast<const ulonglong2*>(xs + (rb + 3) * XSTR);
        const ulonglong2* wp0 = reinterpret_cast<const ulonglong2*>(Ws + (0  + di) * XSTR);
        const ulonglong2* wp1 = reinterpret_cast<const ulonglong2*>(Ws + (16 + di) * XSTR);
        const ulonglong2* wp2 = reinterpret_cast<const ulonglong2*>(Ws + (32 + di) * XSTR);
        const ulonglong2* wp3 = reinterpret_cast<const ulonglong2*>(Ws + (48 + di) * XSTR);

#pragma unroll 8
        for (int q = 0; q < 64; q++) {
            ulonglong2 xv0 = xp0[q], xv1 = xp1[q], xv2 = xp2[q], xv3 = xp3[q];
            ulonglong2 wv0 = wp0[q], wv1 = wp1[q], wv2 = wp2[q], wv3 = wp3[q];
            ffma2(a00, xv0.x, wv0.x); ffma2(a01, xv0.x, wv1.x);
            ffma2(a02, xv0.x, wv2.x); ffma2(a03, xv0.x, wv3.x);
            ffma2(a10, xv1.x, wv0.x); ffma2(a11, xv1.x, wv1.x);
            ffma2(a12, xv1.x, wv2.x); ffma2(a13, xv1.x, wv3.x);
            ffma2(a20, xv2.x, wv0.x); ffma2(a21, xv2.x, wv1.x);
            ffma2(a22, xv2.x, wv2.x); ffma2(a23, xv2.x, wv3.x);
            ffma2(a30, xv3.x, wv0.x); ffma2(a31, xv3.x, wv1.x);
            ffma2(a32, xv3.x, wv2.x); ffma2(a33, xv3.x, wv3.x);
            ffma2(a00, xv0.y, wv0.y); ffma2(a01, xv0.y, wv1.y);
            ffma2(a02, xv0.y, wv2.y); ffma2(a03, xv0.y, wv3.y);
            ffma2(a10, xv1.y, wv0.y); ffma2(a11, xv1.y, wv1.y);
            ffma2(a12, xv1.y, wv2.y); ffma2(a13, xv1.y, wv3.y);
            ffma2(a20, xv2.y, wv0.y); ffma2(a21, xv2.y, wv1.y);
            ffma2(a22, xv2.y, wv2.y); ffma2(a23, xv2.y, wv3.y);
            ffma2(a30, xv3.y, wv0.y); ffma2(a31, xv3.y, wv1.y);
            ffma2(a32, xv3.y, wv2.y); ffma2(a33, xv3.y, wv3.y);
        }

        ull accs[4][4] = {{a00,a01,a02,a03},{a10,a11,a12,a13},
                          {a20,a21,a22,a23},{a30,a31,a32,a33}};
        float* hdst = g_hist + (size_t)t * BATCH * HID;
#pragma unroll
        for (int r = 0; r < 4; r++) {
            float iv = hsum2(accs[r][0]) + z[r][0];
            float fv = hsum2(accs[r][1]) + z[r][1];
            float gv = hsum2(accs[r][2]) + z[r][2];
            float ov = hsum2(accs[r][3]) + z[r][3];
            if (t > 0) { iv += corr4[0]; fv += corr4[1]; gv += corr4[2]; ov += corr4[3]; }
            float cn = sigm(fv) * c[r] + sigm(iv) * tanh_e(gv);
            c[r] = cn;
            hdst[(b0 + rb + r) * HID + d] = sigm(ov) * tanh_e(cn);
        }
        __threadfence();
        __syncthreads();
        if (tid == 0) atomicAdd(&g_cnt[bt], 1);

        // after step 0, swap folded weights Wc in (own GEMM reads done)
        if (t == 0) {
            __syncthreads();
            for (int idx = tid; idx < BT * 64; idx += 256) {
                int lr = idx >> 6, p = idx & 63;
                int j  = (lr >> 4) * HID + d0 + (lr & 15);
                *reinterpret_cast<float4*>(&Ws[lr * XSTR + 4 * p]) =
                    *reinterpret_cast<const float4*>(&g_Wc[(size_t)j * HID + 4 * p]);
            }
        }
    }
}

// ---------------------------------------------------------------------------
// Phase 3: out[b][t][m] = hist[t][b] . W_lin[m] + b_lin[m]
// ---------------------------------------------------------------------------
__global__ void out_proj(const float* __restrict__ Wlin, const float* __restrict__ blin,
                         float* __restrict__ out) {
    __shared__ float hs[16 * HID];
    const int t  = blockIdx.x;
    const int b0 = blockIdx.y * 16;
    const float* src = g_hist + ((size_t)t * BATCH + b0) * HID;
    for (int idx = threadIdx.x; idx < 16 * HID / 2; idx += 272)
        *reinterpret_cast<float2*>(&hs[2 * idx]) =
            *reinterpret_cast<const float2*>(&src[2 * idx]);
    __syncthreads();

    const int bl = threadIdx.x / MF;
    const int m  = threadIdx.x - bl * MF;
    const ull* xr = reinterpret_cast<const ull*>(hs + bl * HID);
    const ull* wl = reinterpret_cast<const ull*>(Wlin + m * HID);
    ull q0 = 0, q1 = 0, q2 = 0, q3 = 0;
#pragma unroll 8
    for (int k = 0; k < 128; k += 4) {
        ffma2(q0, xr[k],     wl[k]);
        ffma2(q1, xr[k + 1], wl[k + 1]);
        ffma2(q2, xr[k + 2], wl[k + 2]);
        ffma2(q3, xr[k + 3], wl[k + 3]);
    }
    float s = blin[m] + hsum2(q0) + hsum2(q1) + hsum2(q2) + hsum2(q3);
    out[((size_t)(b0 + bl) * SEQL + t) * MF + m] = s;
}

// ---------------------------------------------------------------------------
extern "C" void kernel_launch(void* const* d_in, const int* in_sizes, int n_in,
                              void* d_out, int out_size) {
    const float* inseq = (const float*)d_in[0];
    const float* h0    = (const float*)d_in[1];
    const float* c0    = (const float*)d_in[2];
    const float* Wih   = (const float*)d_in[3];
    const float* Whh   = (const float*)d_in[4];
    const float* bih   = (const float*)d_in[5];
    const float* bhh   = (const float*)d_in[6];
    const float* Wlin  = (const float*)d_in[7];
    const float* blin  = (const float*)d_in[8];
    float* out = (float*)d_out;

    cudaFuncSetAttribute(lstm_persistent, cudaFuncAttributeMaxDynamicSharedMemorySize,
                         SMEM_P);

    setup_fold<<<G4, HID>>>(Whh, Wih, Wlin, blin);
    precompute_z<<<dim3(2048, 8), 512>>>(inseq, Wih, bih, bhh);
    lstm_persistent<<<NBT * NDT, 256, SMEM_P>>>(h0, c0, Whh);
    out_proj<<<dim3(SEQL, 32), 272>>>(Wlin, blin, out);
}

// round 7
// speedup vs baseline: 8.3728x; 1.5196x over previous
#include <cuda_runtime.h>
#include <cuda_bf16.h>
#include <cstdint>
#include <math.h>

// ---------------------------------------------------------------------------
// LSTM decoder — tensor-core (mma.sync bf16 split hi/lo, 3-pass) version.
//  conv_a:  in_sequence fp32 -> bf16 hi/lo, rows remapped r = t*512 + b
//  setup:   Wc = W_hh + W_ih[:,:17]@W_lin; split W_hh, Wc, W_ih[:,17:] to hi/lo
//  gemm_z:  Z[r][j] = A[r] . Wz[j] + bias   (mma.sync, 3-pass split)
//  persist: 512 steps, 128 CTAs (8 batch-tiles x 16 dim-tiles):
//           gates = Z + h@W^T (+corr);  mma.sync split;  release/acquire barrier
//  out_proj: out[b][t] = hist[t][b]@W_lin^T + b_lin
// ---------------------------------------------------------------------------

#define BATCH 512
#define SEQL  512
#define HID   256
#define MF    17
#define G4    1024
#define KIN   273
#define NBT   8
#define BT    64
#define NROWS (SEQL * BATCH)

#define KPU 132          // u32 per padded bf16 row (264 bf16; 132 mod 32 == 4)

typedef unsigned long long ull;

__device__ float          g_Z[(size_t)NROWS * G4];        // 1 GB
__device__ float          g_hist[(size_t)SEQL * BATCH * HID];
__device__ float          g_corr[G4];
__device__ int            g_cnt[NBT];
__device__ __nv_bfloat16  g_Ahi[(size_t)NROWS * HID];
__device__ __nv_bfloat16  g_Alo[(size_t)NROWS * HID];
__device__ __nv_bfloat16  g_Wzhi[G4 * HID], g_Wzlo[G4 * HID];
__device__ __nv_bfloat16  g_Whhhi[G4 * HID], g_Whhlo[G4 * HID];
__device__ __nv_bfloat16  g_Wchi[G4 * HID], g_Wclo[G4 * HID];

__device__ __forceinline__ float sigm(float x) {
    return __fdividef(1.0f, 1.0f + __expf(-x));
}
__device__ __forceinline__ float tanh_e(float x) {
    return 1.0f - __fdividef(2.0f, __expf(2.0f * x) + 1.0f);
}
__device__ __forceinline__ void mma_bf16(float* d, const uint32_t* a,
                                         uint32_t b0, uint32_t b1) {
    asm volatile("mma.sync.aligned.m16n8k16.row.col.f32.bf16.bf16.f32 "
        "{%0,%1,%2,%3}, {%4,%5,%6,%7}, {%8,%9}, {%0,%1,%2,%3};"
        : "+f"(d[0]), "+f"(d[1]), "+f"(d[2]), "+f"(d[3])
        : "r"(a[0]), "r"(a[1]), "r"(a[2]), "r"(a[3]), "r"(b0), "r"(b1));
}
__device__ __forceinline__ void red_release(int* p) {
    asm volatile("red.release.gpu.global.add.s32 [%0], 1;" :: "l"(p) : "memory");
}
__device__ __forceinline__ int ld_acquire(const int* p) {
    int v;
    asm volatile("ld.acquire.gpu.global.s32 %0, [%1];" : "=r"(v) : "l"(p) : "memory");
    return v;
}
__device__ __forceinline__ uint32_t pack_hi(float x, float y) {
    __nv_bfloat162 v(__float2bfloat16_rn(x), __float2bfloat16_rn(y));
    return *reinterpret_cast<uint32_t*>(&v);
}
__device__ __forceinline__ uint32_t pack_lo(float x, float y) {
    float hx = __bfloat162float(__float2bfloat16_rn(x));
    float hy = __bfloat162float(__float2bfloat16_rn(y));
    __nv_bfloat162 v(__float2bfloat16_rn(x - hx), __float2bfloat16_rn(y - hy));
    return *reinterpret_cast<uint32_t*>(&v);
}

// ---------------------------------------------------------------------------
// conv_a: fp32 -> hi/lo bf16, row remap r = t*512 + b
// ---------------------------------------------------------------------------
__global__ __launch_bounds__(256)
void conv_a(const float* __restrict__ inseq) {
    size_t i  = (size_t)blockIdx.x * 256 + threadIdx.x;
    size_t e0 = i * 4;
    int r = (int)(e0 >> 8), k = (int)(e0 & 255);
    int b = r & 511, t = r >> 9;
    float4 v = *reinterpret_cast<const float4*>(inseq + ((size_t)(b * SEQL + t)) * HID + k);
    uint32_t h01 = pack_hi(v.x, v.y), h23 = pack_hi(v.z, v.w);
    uint32_t l01 = pack_lo(v.x, v.y), l23 = pack_lo(v.z, v.w);
    *reinterpret_cast<uint2*>(&g_Ahi[e0]) = make_uint2(h01, h23);
    *reinterpret_cast<uint2*>(&g_Alo[e0]) = make_uint2(l01, l23);
}

// ---------------------------------------------------------------------------
// setup: fold Wc, split all weights, corr, counter reset
// ---------------------------------------------------------------------------
__global__ void setup_fold(const float* __restrict__ Whh, const float* __restrict__ Wih,
                           const float* __restrict__ Wlin, const float* __restrict__ blin) {
    const int j = blockIdx.x, k = threadIdx.x;
    float whh = Whh[j * HID + k];
    float wc  = whh;
#pragma unroll
    for (int m = 0; m < MF; m++)
        wc += Wih[j * KIN + m] * Wlin[m * HID + k];
    float wz = Wih[j * KIN + 17 + k];

    __nv_bfloat16 h;
    h = __float2bfloat16_rn(whh);
    g_Whhhi[j * HID + k] = h;
    g_Whhlo[j * HID + k] = __float2bfloat16_rn(whh - __bfloat162float(h));
    h = __float2bfloat16_rn(wc);
    g_Wchi[j * HID + k] = h;
    g_Wclo[j * HID + k] = __float2bfloat16_rn(wc - __bfloat162float(h));
    h = __float2bfloat16_rn(wz);
    g_Wzhi[j * HID + k] = h;
    g_Wzlo[j * HID + k] = __float2bfloat16_rn(wz - __bfloat162float(h));

    if (k == 0) {
        float c = 0.0f;
#pragma unroll
        for (int m = 0; m < MF; m++) c += Wih[j * KIN + m] * blin[m];
        g_corr[j] = c;
    }
    if (j == 0 && k < NBT) g_cnt[k] = 0;
}

// ---------------------------------------------------------------------------
// gemm_z: per CTA: 128 rows x all 1024 cols, K=256. 2048 CTAs, 256 threads.
// A hi/lo resident in smem; W tiles (64 cols) streamed. 3-pass split mma.
// ---------------------------------------------------------------------------
#define SMEM_GZ ((2 * 128 * KPU + 2 * 64 * KPU) * 4)

__global__ __launch_bounds__(256, 1)
void gemm_z(const float* __restrict__ bih, const float* __restrict__ bhh) {
    extern __shared__ uint32_t smu[];
    uint32_t* sAhi = smu;                       // 128 x 132
    uint32_t* sAlo = smu + 128 * KPU;
    uint32_t* sWhi = smu + 256 * KPU;           // 64 x 132
    uint32_t* sWlo = smu + 256 * KPU + 64 * KPU;

    const int tid = threadIdx.x;
    const int wid = tid >> 5, l = tid & 31;
    const int g = l >> 2, c = l & 3;
    const int R0 = blockIdx.x * 128;
    const int mr = wid * 16;                    // warp = one m16 tile

    // stage A hi/lo (128 rows x 512B each)
    for (int idx = tid; idx < 128 * 32; idx += 256) {
        int row = idx >> 5, seg = idx & 31;
        *reinterpret_cast<uint4*>(&sAhi[row * KPU + seg * 4]) =
            *reinterpret_cast<const uint4*>(g_Ahi + (size_t)(R0 + row) * HID + seg * 8);
        *reinterpret_cast<uint4*>(&sAlo[row * KPU + seg * 4]) =
            *reinterpret_cast<const uint4*>(g_Alo + (size_t)(R0 + row) * HID + seg * 8);
    }

    for (int nt = 0; nt < 16; nt++) {
        __syncthreads();   // previous W tile fully consumed
        for (int idx = tid; idx < 64 * 32; idx += 256) {
            int row = idx >> 5, seg = idx & 31;
            *reinterpret_cast<uint4*>(&sWhi[row * KPU + seg * 4]) =
                *reinterpret_cast<const uint4*>(g_Wzhi + (size_t)(nt * 64 + row) * HID + seg * 8);
            *reinterpret_cast<uint4*>(&sWlo[row * KPU + seg * 4]) =
                *reinterpret_cast<const uint4*>(g_Wzlo + (size_t)(nt * 64 + row) * HID + seg * 8);
        }
        __syncthreads();

        float d[8][4];
#pragma unroll
        for (int n8 = 0; n8 < 8; n8++)
#pragma unroll
            for (int q = 0; q < 4; q++) d[n8][q] = 0.0f;

        for (int p = 0; p < 3; p++) {
            const uint32_t* As = (p == 2) ? sAlo : sAhi;
            const uint32_t* Bs = (p == 1) ? sWlo : sWhi;
#pragma unroll
            for (int ks = 0; ks < 16; ks++) {
                const int k2 = ks * 8;
                uint32_t a[4];
                a[0] = As[(mr + g)     * KPU + k2 + c];
                a[1] = As[(mr + g + 8) * KPU + k2 + c];
                a[2] = As[(mr + g)     * KPU + k2 + 4 + c];
                a[3] = As[(mr + g + 8) * KPU + k2 + 4 + c];
#pragma unroll
                for (int n8 = 0; n8 < 8; n8++) {
                    uint32_t b0 = Bs[(n8 * 8 + g) * KPU + k2 + c];
                    uint32_t b1 = Bs[(n8 * 8 + g) * KPU + k2 + 4 + c];
                    mma_bf16(d[n8], a, b0, b1);
                }
            }
        }

        // epilogue: + bias, direct STG.64
#pragma unroll
        for (int n8 = 0; n8 < 8; n8++) {
            int col = nt * 64 + n8 * 8 + 2 * c;
            float bs0 = __ldg(bih + col) + __ldg(bhh + col);
            float bs1 = __ldg(bih + col + 1) + __ldg(bhh + col + 1);
            float* z0 = g_Z + (size_t)(R0 + mr + g) * G4 + col;
            float* z1 = g_Z + (size_t)(R0 + mr + g + 8) * G4 + col;
            *reinterpret_cast<float2*>(z0) = make_float2(d[n8][0] + bs0, d[n8][1] + bs1);
            *reinterpret_cast<float2*>(z1) = make_float2(d[n8][2] + bs0, d[n8][3] + bs1);
        }
    }
}

// ---------------------------------------------------------------------------
// persistent recurrence: 128 CTAs (8 bt x 16 dt), 256 threads.
// GEMM warp: mt=wid&3 (m16 rows), nh=wid>>2 (n32 cols). Epilogue thread:
// row = tid>>2, dims dg..dg+3 (dg=(tid&3)*4); c-state float4 in registers.
// ---------------------------------------------------------------------------
#define SMEM_P ((4 * 64 * KPU) * 4 + 64 * 66 * 4)

__global__ __launch_bounds__(256, 1)
void lstm_persistent(const float* __restrict__ h0, const float* __restrict__ c0) {
    extern __shared__ uint32_t smu[];
    uint32_t* sWhi = smu;                        // 64 x 132 (n = gate*16+dl)
    uint32_t* sWlo = smu + 64 * KPU;
    uint32_t* sXhi = smu + 128 * KPU;            // 64 x 132 (batch rows)
    uint32_t* sXlo = smu + 192 * KPU;
    float*    S    = reinterpret_cast<float*>(smu + 256 * KPU);  // 64 x 66

    const int tid = threadIdx.x;
    const int wid = tid >> 5, l = tid & 31;
    const int g = l >> 2, c = l & 3;
    const int mt = wid & 3, nh = wid >> 2;
    const int bt = blockIdx.x >> 4, dt = blockIdx.x & 15;
    const int b0 = bt * BT, d0 = dt * 16;

    // epilogue-role indices
    const int erow = tid >> 2;
    const int edg  = (tid & 3) * 4;

    float4 c4 = *reinterpret_cast<const float4*>(c0 + (size_t)(b0 + erow) * HID + d0 + edg);
    float4 cr[4];
#pragma unroll
    for (int ga = 0; ga < 4; ga++)
        cr[ga] = *reinterpret_cast<const float4*>(g_corr + ga * HID + d0 + edg);

    // stage W_hh split (step 0); smem row n = gate*16 + dlocal
    for (int idx = tid; idx < 64 * 32; idx += 256) {
        int n = idx >> 5, seg = idx & 31;
        size_t j = (size_t)((n >> 4) * HID + d0 + (n & 15));
        *reinterpret_cast<uint4*>(&sWhi[n * KPU + seg * 4]) =
            *reinterpret_cast<const uint4*>(g_Whhhi + j * HID + seg * 8);
        *reinterpret_cast<uint4*>(&sWlo[n * KPU + seg * 4]) =
            *reinterpret_cast<const uint4*>(g_Whhlo + j * HID + seg * 8);
    }

    for (int t = 0; t < SEQL; t++) {
        // Z prefetch (h-independent): 4 gates x 4 dims
        float4 zq[4];
        {
            const float* zb = g_Z + ((size_t)t * BATCH + b0 + erow) * G4 + d0 + edg;
#pragma unroll
            for (int ga = 0; ga < 4; ga++)
                zq[ga] = __ldcg(reinterpret_cast<const float4*>(zb + ga * HID));
        }

        if (t > 0) {
            if (tid == 0) {
                const int target = 16 * t;
                while (ld_acquire(&g_cnt[bt]) < target) { }
            }
            __syncthreads();
        }

        // stage x = h_{t-1}: fp32 -> hi/lo bf16 smem
        {
            const float* src = (t == 0) ? (h0 + (size_t)b0 * HID)
                                        : (g_hist + ((size_t)(t - 1) * BATCH + b0) * HID);
            for (int idx = tid; idx < 64 * 64; idx += 256) {
                int row = idx >> 6, seg = idx & 63;      // seg: float4 within row
                float4 v = __ldcg(reinterpret_cast<const float4*>(src + row * HID + seg * 4));
                int base = row * KPU + seg * 2;
                *reinterpret_cast<uint2*>(&sXhi[base]) =
                    make_uint2(pack_hi(v.x, v.y), pack_hi(v.z, v.w));
                *reinterpret_cast<uint2*>(&sXlo[base]) =
                    make_uint2(pack_lo(v.x, v.y), pack_lo(v.z, v.w));
            }
        }
        __syncthreads();

        // gates GEMM: warp m16 x n32, K=256, 3-pass split
        float d[4][4];
#pragma unroll
        for (int n8 = 0; n8 < 4; n8++)
#pragma unroll
            for (int q = 0; q < 4; q++) d[n8][q] = 0.0f;

        for (int p = 0; p < 3; p++) {
            const uint32_t* As = (p == 2) ? sXlo : sXhi;
            const uint32_t* Bs = (p == 1) ? sWlo : sWhi;
#pragma unroll
            for (int ks = 0; ks < 16; ks++) {
                const int k2 = ks * 8;
                uint32_t a[4];
                a[0] = As[(mt * 16 + g)     * KPU + k2 + c];
                a[1] = As[(mt * 16 + g + 8) * KPU + k2 + c];
                a[2] = As[(mt * 16 + g)     * KPU + k2 + 4 + c];
                a[3] = As[(mt * 16 + g + 8) * KPU + k2 + 4 + c];
#pragma unroll
                for (int n8 = 0; n8 < 4; n8++) {
                    uint32_t b0 = Bs[(nh * 32 + n8 * 8 + g) * KPU + k2 + c];
                    uint32_t b1 = Bs[(nh * 32 + n8 * 8 + g) * KPU + k2 + 4 + c];
                    mma_bf16(d[n8], a, b0, b1);
                }
            }
        }

        // stage acc -> S for gate-quad remap
#pragma unroll
        for (int n8 = 0; n8 < 4; n8++) {
            int scol = nh * 32 + n8 * 8 + 2 * c;
            *reinterpret_cast<float2*>(&S[(mt * 16 + g) * 66 + scol]) =
                make_float2(d[n8][0], d[n8][1]);
            *reinterpret_cast<float2*>(&S[(mt * 16 + g + 8) * 66 + scol]) =
                make_float2(d[n8][2], d[n8][3]);
        }
        __syncthreads();

        // LSTM elementwise: thread = (erow, dims edg..edg+3)
        {
            float hv[4];
            const float* zz = reinterpret_cast<const float*>(zq);
            const float* cc = reinterpret_cast<const float*>(cr);
            float* cs = reinterpret_cast<float*>(&c4);
#pragma unroll
            for (int j = 0; j < 4; j++) {
                float iv = S[erow * 66 + 0 * 16 + edg + j] + zz[0 * 4 + j];
                float fv = S[erow * 66 + 1 * 16 + edg + j] + zz[1 * 4 + j];
                float gv = S[erow * 66 + 2 * 16 + edg + j] + zz[2 * 4 + j];
                float ov = S[erow * 66 + 3 * 16 + edg + j] + zz[3 * 4 + j];
                if (t > 0) {
                    iv += cc[0 * 4 + j]; fv += cc[1 * 4 + j];
                    gv += cc[2 * 4 + j]; ov += cc[3 * 4 + j];
                }
                float cn = sigm(fv) * cs[j] + sigm(iv) * tanh_e(gv);
                cs[j] = cn;
                hv[j] = sigm(ov) * tanh_e(cn);
            }
            *reinterpret_cast<float4*>(
                g_hist + ((size_t)t * BATCH + b0 + erow) * HID + d0 + edg) =
                make_float4(hv[0], hv[1], hv[2], hv[3]);
        }
        __syncthreads();
        if (tid == 0) red_release(&g_cnt[bt]);

        // swap folded weights in after step 0
        if (t == 0) {
            for (int idx = tid; idx < 64 * 32; idx += 256) {
                int n = idx >> 5, seg = idx & 31;
                size_t j = (size_t)((n >> 4) * HID + d0 + (n & 15));
                *reinterpret_cast<uint4*>(&sWhi[n * KPU + seg * 4]) =
                    *reinterpret_cast<const uint4*>(g_Wchi + j * HID + seg * 8);
                *reinterpret_cast<uint4*>(&sWlo[n * KPU + seg * 4]) =
                    *reinterpret_cast<const uint4*>(g_Wclo + j * HID + seg * 8);
            }
        }
    }
}

// ---------------------------------------------------------------------------
// out_proj: out[b][t][m] = hist[t][b] . W_lin[m] + b_lin[m]
// ---------------------------------------------------------------------------
__global__ void out_proj(const float* __restrict__ Wlin, const float* __restrict__ blin,
                         float* __restrict__ out) {
    __shared__ float hs[16 * HID];
    const int t  = blockIdx.x;
    const int b0 = blockIdx.y * 16;
    const float* src = g_hist + ((size_t)t * BATCH + b0) * HID;
    for (int idx = threadIdx.x; idx < 16 * HID / 4; idx += 272)
        *reinterpret_cast<float4*>(&hs[4 * idx]) =
            *reinterpret_cast<const float4*>(&src[4 * idx]);
    __syncthreads();

    const int bl = threadIdx.x / MF;
    const int m  = threadIdx.x - bl * MF;
    const float* xr = hs + bl * HID;
    const float* wl = Wlin + m * HID;
    float s0 = 0, s1 = 0, s2 = 0, s3 = 0;
#pragma unroll 8
    for (int k = 0; k < HID; k += 4) {
        s0 += xr[k] * wl[k];     s1 += xr[k + 1] * wl[k + 1];
        s2 += xr[k + 2] * wl[k + 2]; s3 += xr[k + 3] * wl[k + 3];
    }
    out[((size_t)(b0 + bl) * SEQL + t) * MF + m] = blin[m] + s0 + s1 + s2 + s3;
}

// ---------------------------------------------------------------------------
extern "C" void kernel_launch(void* const* d_in, const int* in_sizes, int n_in,
                              void* d_out, int out_size) {
    const float* inseq = (const float*)d_in[0];
    const float* h0    = (const float*)d_in[1];
    const float* c0    = (const float*)d_in[2];
    const float* Wih   = (const float*)d_in[3];
    const float* Whh   = (const float*)d_in[4];
    const float* bih   = (const float*)d_in[5];
    const float* bhh   = (const float*)d_in[6];
    const float* Wlin  = (const float*)d_in[7];
    const float* blin  = (const float*)d_in[8];
    float* out = (float*)d_out;

    cudaFuncSetAttribute(gemm_z, cudaFuncAttributeMaxDynamicSharedMemorySize, SMEM_GZ);
    cudaFuncSetAttribute(lstm_persistent, cudaFuncAttributeMaxDynamicSharedMemorySize, SMEM_P);

    setup_fold<<<G4, HID>>>(Whh, Wih, Wlin, blin);
    conv_a<<<65536, 256>>>(inseq);
    gemm_z<<<2048, 256, SMEM_GZ>>>(bih, bhh);
    lstm_persistent<<<NBT * 16, 256, SMEM_P>>>(h0, c0);
    out_proj<<<dim3(SEQL, 32), 272>>>(Wlin, blin, out);
}

// round 8
// speedup vs baseline: 8.5193x; 1.0175x over previous
#include <cuda_runtime.h>
#include <cuda_bf16.h>
#include <cstdint>
#include <math.h>

// ---------------------------------------------------------------------------
// LSTM decoder — mma.sync bf16 split hi/lo (3-pass), ldmatrix, m32n32 warps,
// gate-permuted W for register-resident epilogue, bf16 h exchange.
// ---------------------------------------------------------------------------

#define BATCH 512
#define SEQL  512
#define HID   256
#define MF    17
#define G4    1024
#define KIN   273
#define NBT   8
#define BT    64
#define NROWS (SEQL * BATCH)
#define KPU   132            // u32 per bf16 row (264 bf16); 132*4=528B: LDSM-clean

typedef unsigned long long ull;

__device__ float          g_Z[(size_t)NROWS * G4];          // 1 GB
__device__ float          g_hist[(size_t)SEQL * BATCH * HID];
__device__ float          g_corr[G4];
__device__ int            g_cnt[NBT];
__device__ __nv_bfloat16  g_Ahi[(size_t)NROWS * HID];
__device__ __nv_bfloat16  g_Alo[(size_t)NROWS * HID];
__device__ __nv_bfloat16  g_hh_hi[(size_t)SEQL * BATCH * HID];  // h history bf16
__device__ __nv_bfloat16  g_hh_lo[(size_t)SEQL * BATCH * HID];
__device__ __nv_bfloat16  g_Wzhi[G4 * HID], g_Wzlo[G4 * HID];   // z-proj (plain)
__device__ __nv_bfloat16  g_Wq_hi[G4 * HID], g_Wq_lo[G4 * HID]; // Whh (permuted)
__device__ __nv_bfloat16  g_Wp_hi[G4 * HID], g_Wp_lo[G4 * HID]; // Wc  (permuted)

__device__ __forceinline__ float sigm(float x) {
    return __fdividef(1.0f, 1.0f + __expf(-x));
}
__device__ __forceinline__ float tanh_e(float x) {
    return 1.0f - __fdividef(2.0f, __expf(2.0f * x) + 1.0f);
}
__device__ __forceinline__ void mma_bf16(float* d, const uint32_t* a,
                                         uint32_t b0, uint32_t b1) {
    asm volatile("mma.sync.aligned.m16n8k16.row.col.f32.bf16.bf16.f32 "
        "{%0,%1,%2,%3}, {%4,%5,%6,%7}, {%8,%9}, {%0,%1,%2,%3};"
        : "+f"(d[0]), "+f"(d[1]), "+f"(d[2]), "+f"(d[3])
        : "r"(a[0]), "r"(a[1]), "r"(a[2]), "r"(a[3]), "r"(b0), "r"(b1));
}
#define LDSM4(r0, r1, r2, r3, addr) \
    asm volatile("ldmatrix.sync.aligned.m8n8.x4.shared.b16 {%0,%1,%2,%3}, [%4];" \
        : "=r"(r0), "=r"(r1), "=r"(r2), "=r"(r3) : "r"(addr))
__device__ __forceinline__ void red_release(int* p) {
    asm volatile("red.release.gpu.global.add.s32 [%0], 1;" :: "l"(p) : "memory");
}
__device__ __forceinline__ int ld_acquire(const int* p) {
    int v;
    asm volatile("ld.acquire.gpu.global.s32 %0, [%1];" : "=r"(v) : "l"(p) : "memory");
    return v;
}
__device__ __forceinline__ uint32_t smem_u32(const void* p) {
    uint32_t a;
    asm("{ .reg .u64 t; cvta.to.shared.u64 t, %1; cvt.u32.u64 %0, t; }" : "=r"(a) : "l"(p));
    return a;
}
__device__ __forceinline__ uint32_t pack_hi(float x, float y) {
    __nv_bfloat162 v(__float2bfloat16_rn(x), __float2bfloat16_rn(y));
    return *reinterpret_cast<uint32_t*>(&v);
}
__device__ __forceinline__ uint32_t pack_lo(float x, float y) {
    float hx = __bfloat162float(__float2bfloat16_rn(x));
    float hy = __bfloat162float(__float2bfloat16_rn(y));
    __nv_bfloat162 v(__float2bfloat16_rn(x - hx), __float2bfloat16_rn(y - hy));
    return *reinterpret_cast<uint32_t*>(&v);
}

// ---------------------------------------------------------------------------
// conv_a: fp32 -> hi/lo bf16, row remap r = t*512 + b
// ---------------------------------------------------------------------------
__global__ __launch_bounds__(256)
void conv_a(const float* __restrict__ inseq) {
    size_t i  = (size_t)blockIdx.x * 256 + threadIdx.x;
    size_t e0 = i * 4;
    int r = (int)(e0 >> 8), k = (int)(e0 & 255);
    int b = r & 511, t = r >> 9;
    float4 v = *reinterpret_cast<const float4*>(inseq + ((size_t)(b * SEQL + t)) * HID + k);
    *reinterpret_cast<uint2*>(&g_Ahi[e0]) = make_uint2(pack_hi(v.x, v.y), pack_hi(v.z, v.w));
    *reinterpret_cast<uint2*>(&g_Alo[e0]) = make_uint2(pack_lo(v.x, v.y), pack_lo(v.z, v.w));
}

// ---------------------------------------------------------------------------
// setup: Wc fold, splits (plain Wz; permuted Whh/Wc), corr, counters.
// Permutation: row j=(gate,dim) stored at [dt][nl] with nl = nh*32+gate*8+cc,
// dt=dim>>4, dl=dim&15, nh=dl>>3, cc=dl&7 -> mma acc quads = gate quads.
// ---------------------------------------------------------------------------
__global__ void setup_fold(const float* __restrict__ Whh, const float* __restrict__ Wih,
                           const float* __restrict__ Wlin, const float* __restrict__ blin) {
    const int j = blockIdx.x, k = threadIdx.x;
    const int gate = j >> 8, dim = j & 255;
    const int dt = dim >> 4, dl = dim & 15;
    const int nl = (dl >> 3) * 32 + gate * 8 + (dl & 7);
    const size_t pidx = ((size_t)(dt * 64 + nl)) * HID + k;

    float whh = Whh[j * HID + k];
    float wc  = whh;
#pragma unroll
    for (int m = 0; m < MF; m++)
        wc += Wih[j * KIN + m] * Wlin[m * HID + k];
    float wz = Wih[j * KIN + 17 + k];

    __nv_bfloat16 h;
    h = __float2bfloat16_rn(whh);
    g_Wq_hi[pidx] = h;
    g_Wq_lo[pidx] = __float2bfloat16_rn(whh - __bfloat162float(h));
    h = __float2bfloat16_rn(wc);
    g_Wp_hi[pidx] = h;
    g_Wp_lo[pidx] = __float2bfloat16_rn(wc - __bfloat162float(h));
    h = __float2bfloat16_rn(wz);
    g_Wzhi[j * HID + k] = h;
    g_Wzlo[j * HID + k] = __float2bfloat16_rn(wz - __bfloat162float(h));

    if (k == 0) {
        float c = 0.0f;
#pragma unroll
        for (int m = 0; m < MF; m++) c += Wih[j * KIN + m] * blin[m];
        g_corr[j] = c;
    }
    if (j == 0 && k < NBT) g_cnt[k] = 0;
}

// ---------------------------------------------------------------------------
// gemm_z: 2048 CTAs x (128 rows, 1024 cols), K=256, 3-pass split.
// 8 warps, each m32 x n32 (mt2 = wid&3, nh = wid>>2). ldmatrix loads.
// ---------------------------------------------------------------------------
#define GZ_A_U   (128 * KPU)
#define GZ_W_OFF (2 * GZ_A_U)                 // u32 offset of W hi
#define GZ_W_U   (64 * KPU)
#define SMEM_GZ  ((2 * GZ_A_U + 2 * GZ_W_U) * 4)

__global__ __launch_bounds__(256, 1)
void gemm_z(const float* __restrict__ bih, const float* __restrict__ bhh) {
    extern __shared__ uint32_t smu[];
    const uint32_t ubase = smem_u32(smu);
    const int tid = threadIdx.x;
    const int wid = tid >> 5, l = tid & 31;
    const int g = l >> 2, c = l & 3;
    const int mt2 = wid & 3, nh = wid >> 2;
    const int R0 = blockIdx.x * 128;

    // stage A hi/lo
    for (int idx = tid; idx < 128 * 32; idx += 256) {
        int row = idx >> 5, seg = idx & 31;
        *reinterpret_cast<uint4*>(&smu[row * KPU + seg * 4]) =
            *reinterpret_cast<const uint4*>(g_Ahi + (size_t)(R0 + row) * HID + seg * 8);
        *reinterpret_cast<uint4*>(&smu[GZ_A_U + row * KPU + seg * 4]) =
            *reinterpret_cast<const uint4*>(g_Alo + (size_t)(R0 + row) * HID + seg * 8);
    }

    // ldmatrix lane addresses
    uint32_t aAd[2], wBd[2];
#pragma unroll
    for (int h = 0; h < 2; h++)
        aAd[h] = ubase + (uint32_t)((mt2 * 32 + h * 16 + (l & 15)) * KPU) * 4 + (l >> 4) * 16;
#pragma unroll
    for (int p2 = 0; p2 < 2; p2++)
        wBd[p2] = ubase + (uint32_t)(GZ_W_OFF + (nh * 32 + p2 * 16 + (l >> 4) * 8 + (l & 7)) * KPU) * 4
                + ((l >> 3) & 1) * 16;

    const uint32_t ALO = (uint32_t)GZ_A_U * 4;
    const uint32_t WLO = (uint32_t)GZ_W_U * 4;

    for (int nt = 0; nt < 16; nt++) {
        __syncthreads();
        for (int idx = tid; idx < 64 * 32; idx += 256) {
            int row = idx >> 5, seg = idx & 31;
            *reinterpret_cast<uint4*>(&smu[GZ_W_OFF + row * KPU + seg * 4]) =
                *reinterpret_cast<const uint4*>(g_Wzhi + (size_t)(nt * 64 + row) * HID + seg * 8);
            *reinterpret_cast<uint4*>(&smu[GZ_W_OFF + GZ_W_U + row * KPU + seg * 4]) =
                *reinterpret_cast<const uint4*>(g_Wzlo + (size_t)(nt * 64 + row) * HID + seg * 8);
        }
        __syncthreads();

        float d[2][4][4];
#pragma unroll
        for (int h = 0; h < 2; h++)
#pragma unroll
            for (int n8 = 0; n8 < 4; n8++)
#pragma unroll
                for (int q = 0; q < 4; q++) d[h][n8][q] = 0.0f;

        for (int p = 0; p < 3; p++) {
            const uint32_t aoff = (p == 2) ? ALO : 0u;
            const uint32_t boff = (p == 1) ? WLO : 0u;
#pragma unroll
            for (int ks = 0; ks < 16; ks++) {
                const uint32_t kb = ks * 32;
                uint32_t u0, u1, u2, u3, v0, v1, v2, v3, a0[4], a1[4];
                LDSM4(a0[0], a0[1], a0[2], a0[3], aAd[0] + aoff + kb);
                LDSM4(a1[0], a1[1], a1[2], a1[3], aAd[1] + aoff + kb);
                LDSM4(u0, u1, u2, u3, wBd[0] + boff + kb);
                LDSM4(v0, v1, v2, v3, wBd[1] + boff + kb);
                mma_bf16(d[0][0], a0, u0, u1); mma_bf16(d[0][1], a0, u2, u3);
                mma_bf16(d[0][2], a0, v0, v1); mma_bf16(d[0][3], a0, v2, v3);
                mma_bf16(d[1][0], a1, u0, u1); mma_bf16(d[1][1], a1, u2, u3);
                mma_bf16(d[1][2], a1, v0, v1); mma_bf16(d[1][3], a1, v2, v3);
            }
        }

#pragma unroll
        for (int h = 0; h < 2; h++)
#pragma unroll
            for (int n8 = 0; n8 < 4; n8++) {
                int col = nt * 64 + nh * 32 + n8 * 8 + 2 * c;
                float bs0 = __ldg(bih + col) + __ldg(bhh + col);
                float bs1 = __ldg(bih + col + 1) + __ldg(bhh + col + 1);
                int r0 = R0 + mt2 * 32 + h * 16 + g;
                *reinterpret_cast<float2*>(g_Z + (size_t)r0 * G4 + col) =
                    make_float2(d[h][n8][0] + bs0, d[h][n8][1] + bs1);
                *reinterpret_cast<float2*>(g_Z + (size_t)(r0 + 8) * G4 + col) =
                    make_float2(d[h][n8][2] + bs0, d[h][n8][3] + bs1);
            }
    }
}

// ---------------------------------------------------------------------------
// persistent: 128 CTAs (8 bt x 16 dt), 256 threads; warps 0-3 do m32n32 GEMM.
// smem: W hi/lo (64 x KPU each) then X hi/lo.
// ---------------------------------------------------------------------------
#define P_BUF_U (64 * KPU)
#define P_X_OFF (2 * P_BUF_U)
#define SMEM_P  (4 * P_BUF_U * 4)

__global__ __launch_bounds__(256, 1)
void lstm_persistent(const float* __restrict__ h0, const float* __restrict__ c0) {
    extern __shared__ uint32_t smu[];
    const uint32_t ubase = smem_u32(smu);
    const int tid = threadIdx.x;
    const int wid = tid >> 5, l = tid & 31;
    const int g = l >> 2, c = l & 3;
    const int mt2 = wid & 1, nh = wid >> 1;           // valid for wid < 4
    const int bt = blockIdx.x >> 4, dt = blockIdx.x & 15;
    const int bb0 = bt * BT, d0 = dt * 16;
    const int dl0 = nh * 8 + 2 * c;
    const bool gemmw = (wid < 4);

    // ldmatrix lane addresses (X rows = batch, W rows = permuted gates)
    uint32_t aXd[2], wBd[2];
#pragma unroll
    for (int h = 0; h < 2; h++)
        aXd[h] = ubase + (uint32_t)(P_X_OFF + (mt2 * 32 + h * 16 + (l & 15)) * KPU) * 4
               + (l >> 4) * 16;
#pragma unroll
    for (int p2 = 0; p2 < 2; p2++)
        wBd[p2] = ubase + (uint32_t)((nh * 32 + p2 * 16 + (l >> 4) * 8 + (l & 7)) * KPU) * 4
                + ((l >> 3) & 1) * 16;
    const uint32_t LOFF = (uint32_t)P_BUF_U * 4;

    // per-thread state (warps 0-3): 4 rows x 2 dims
    float2 cst[2][2], cr[4];
    if (gemmw) {
#pragma unroll
        for (int h = 0; h < 2; h++)
#pragma unroll
            for (int rh = 0; rh < 2; rh++) {
                int row = mt2 * 32 + h * 16 + rh * 8 + g;
                cst[h][rh] = *reinterpret_cast<const float2*>(
                    c0 + (size_t)(bb0 + row) * HID + d0 + dl0);
            }
#pragma unroll
        for (int ga = 0; ga < 4; ga++)
            cr[ga] = *reinterpret_cast<const float2*>(g_corr + ga * HID + d0 + dl0);
    }

    // stage permuted W_hh (step 0)
    for (int idx = tid; idx < 64 * 32; idx += 256) {
        int row = idx >> 5, seg = idx & 31;
        size_t src = (size_t)(dt * 64 + row) * HID + seg * 8;
        *reinterpret_cast<uint4*>(&smu[row * KPU + seg * 4]) =
            *reinterpret_cast<const uint4*>(g_Wq_hi + src);
        *reinterpret_cast<uint4*>(&smu[P_BUF_U + row * KPU + seg * 4]) =
            *reinterpret_cast<const uint4*>(g_Wq_lo + src);
    }

    for (int t = 0; t < SEQL; t++) {
        // Z prefetch (h-independent, before spin): 4 rows x 4 gates float2
        float2 zz[2][2][4];
        if (gemmw) {
#pragma unroll
            for (int h = 0; h < 2; h++)
#pragma unroll
                for (int rh = 0; rh < 2; rh++) {
                    int row = mt2 * 32 + h * 16 + rh * 8 + g;
                    const float* zb = g_Z + ((size_t)t * BATCH + bb0 + row) * G4 + d0 + dl0;
#pragma unroll
                    for (int ga = 0; ga < 4; ga++)
                        zz[h][rh][ga] = __ldcg(
                            reinterpret_cast<const float2*>(zb + ga * HID));
                }
        }

        if (t > 0) {
            if (tid == 0) {
                const int target = 16 * t;
                while (ld_acquire(&g_cnt[bt]) < target) { }
            }
            __syncthreads();
        }

        // stage X = h_{t-1} (bf16 hi/lo straight copy; t=0 converts h0)
        if (t == 0) {
            const float* src = h0 + (size_t)bb0 * HID;
            for (int idx = tid; idx < 64 * 64; idx += 256) {
                int row = idx >> 6, seg = idx & 63;
                float4 v = *reinterpret_cast<const float4*>(src + row * HID + seg * 4);
                int base = P_X_OFF + row * KPU + seg * 2;
                *reinterpret_cast<uint2*>(&smu[base]) =
                    make_uint2(pack_hi(v.x, v.y), pack_hi(v.z, v.w));
                *reinterpret_cast<uint2*>(&smu[base + P_BUF_U]) =
                    make_uint2(pack_lo(v.x, v.y), pack_lo(v.z, v.w));
            }
        } else {
            const uint4* sH = reinterpret_cast<const uint4*>(
                g_hh_hi + ((size_t)(t - 1) * BATCH + bb0) * HID);
            const uint4* sL = reinterpret_cast<const uint4*>(
                g_hh_lo + ((size_t)(t - 1) * BATCH + bb0) * HID);
            for (int idx = tid; idx < 64 * 32; idx += 256) {
                int row = idx >> 5, seg = idx & 31;
                *reinterpret_cast<uint4*>(&smu[P_X_OFF + row * KPU + seg * 4]) = sH[idx];
                *reinterpret_cast<uint4*>(&smu[P_X_OFF + P_BUF_U + row * KPU + seg * 4]) = sL[idx];
            }
        }
        __syncthreads();

        if (gemmw) {
            float d[2][4][4];
#pragma unroll
            for (int h = 0; h < 2; h++)
#pragma unroll
                for (int n8 = 0; n8 < 4; n8++)
#pragma unroll
                    for (int q = 0; q < 4; q++) d[h][n8][q] = 0.0f;

            for (int p = 0; p < 3; p++) {
                const uint32_t aoff = (p == 2) ? LOFF : 0u;
                const uint32_t boff = (p == 1) ? LOFF : 0u;
#pragma unroll
                for (int ks = 0; ks < 16; ks++) {
                    const uint32_t kb = ks * 32;
                    uint32_t u0, u1, u2, u3, v0, v1, v2, v3, a0[4], a1[4];
                    LDSM4(a0[0], a0[1], a0[2], a0[3], aXd[0] + aoff + kb);
                    LDSM4(a1[0], a1[1], a1[2], a1[3], aXd[1] + aoff + kb);
                    LDSM4(u0, u1, u2, u3, wBd[0] + boff + kb);
                    LDSM4(v0, v1, v2, v3, wBd[1] + boff + kb);
                    mma_bf16(d[0][0], a0, u0, u1); mma_bf16(d[0][1], a0, u2, u3);
                    mma_bf16(d[0][2], a0, v0, v1); mma_bf16(d[0][3], a0, v2, v3);
                    mma_bf16(d[1][0], a1, u0, u1); mma_bf16(d[1][1], a1, u2, u3);
                    mma_bf16(d[1][2], a1, v0, v1); mma_bf16(d[1][3], a1, v2, v3);
                }
            }

            // register-resident epilogue: quads ARE gate quads
#pragma unroll
            for (int h = 0; h < 2; h++)
#pragma unroll
                for (int rh = 0; rh < 2; rh++) {
                    int row = mt2 * 32 + h * 16 + rh * 8 + g;
                    const float* zp = &zz[h][rh][0].x;
                    const float* cp = &cr[0].x;
                    float* cs = &cst[h][rh].x;
                    float hv[2];
#pragma unroll
                    for (int j = 0; j < 2; j++) {
                        int q = rh * 2 + j;
                        float iv = d[h][0][q] + zp[0 + j];
                        float fv = d[h][1][q] + zp[2 + j];
                        float gv = d[h][2][q] + zp[4 + j];
                        float ov = d[h][3][q] + zp[6 + j];
                        if (t > 0) {
                            iv += cp[0 + j]; fv += cp[2 + j];
                            gv += cp[4 + j]; ov += cp[6 + j];
                        }
                        float cn = sigm(fv) * cs[j] + sigm(iv) * tanh_e(gv);
                        cs[j] = cn;
                        hv[j] = sigm(ov) * tanh_e(cn);
                    }
                    size_t base = ((size_t)t * BATCH + bb0 + row) * HID + d0 + dl0;
                    *reinterpret_cast<float2*>(g_hist + base) = make_float2(hv[0], hv[1]);
                    reinterpret_cast<uint32_t*>(g_hh_hi)[base >> 1] = pack_hi(hv[0], hv[1]);
                    reinterpret_cast<uint32_t*>(g_hh_lo)[base >> 1] = pack_lo(hv[0], hv[1]);
                }
        }
        __syncthreads();
        if (tid == 0) red_release(&g_cnt[bt]);

        // swap folded weights in after step 0
        if (t == 0) {
            for (int idx = tid; idx < 64 * 32; idx += 256) {
                int row = idx >> 5, seg = idx & 31;
                size_t src = (size_t)(dt * 64 + row) * HID + seg * 8;
                *reinterpret_cast<uint4*>(&smu[row * KPU + seg * 4]) =
                    *reinterpret_cast<const uint4*>(g_Wp_hi + src);
                *reinterpret_cast<uint4*>(&smu[P_BUF_U + row * KPU + seg * 4]) =
                    *reinterpret_cast<const uint4*>(g_Wp_lo + src);
            }
        }
    }
}

// ---------------------------------------------------------------------------
// out_proj: out[b][t][m] = hist[t][b] . W_lin[m] + b_lin[m]
// ---------------------------------------------------------------------------
__global__ void out_proj(const float* __restrict__ Wlin, const float* __restrict__ blin,
                         float* __restrict__ out) {
    __shared__ float hs[16 * HID];
    const int t  = blockIdx.x;
    const int b0 = blockIdx.y * 16;
    const float* src = g_hist + ((size_t)t * BATCH + b0) * HID;
    for (int idx = threadIdx.x; idx < 16 * HID / 4; idx += 272)
        *reinterpret_cast<float4*>(&hs[4 * idx]) =
            *reinterpret_cast<const float4*>(&src[4 * idx]);
    __syncthreads();

    const int bl = threadIdx.x / MF;
    const int m  = threadIdx.x - bl * MF;
    const float* xr = hs + bl * HID;
    const float* wl = Wlin + m * HID;
    float s0 = 0, s1 = 0, s2 = 0, s3 = 0;
#pragma unroll 8
    for (int k = 0; k < HID; k += 4) {
        s0 += xr[k] * wl[k];         s1 += xr[k + 1] * wl[k + 1];
        s2 += xr[k + 2] * wl[k + 2]; s3 += xr[k + 3] * wl[k + 3];
    }
    out[((size_t)(b0 + bl) * SEQL + t) * MF + m] = blin[m] + s0 + s1 + s2 + s3;
}

// ---------------------------------------------------------------------------
extern "C" void kernel_launch(void* const* d_in, const int* in_sizes, int n_in,
                              void* d_out, int out_size) {
    const float* inseq = (const float*)d_in[0];
    const float* h0    = (const float*)d_in[1];
    const float* c0    = (const float*)d_in[2];
    const float* Wih   = (const float*)d_in[3];
    const float* Whh   = (const float*)d_in[4];
    const float* bih   = (const float*)d_in[5];
    const float* bhh   = (const float*)d_in[6];
    const float* Wlin  = (const float*)d_in[7];
    const float* blin  = (const float*)d_in[8];
    float* out = (float*)d_out;

    cudaFuncSetAttribute(gemm_z, cudaFuncAttributeMaxDynamicSharedMemorySize, SMEM_GZ);
    cudaFuncSetAttribute(lstm_persistent, cudaFuncAttributeMaxDynamicSharedMemorySize, SMEM_P);

    setup_fold<<<G4, HID>>>(Whh, Wih, Wlin, blin);
    conv_a<<<65536, 256>>>(inseq);
    gemm_z<<<2048, 256, SMEM_GZ>>>(bih, bhh);
    lstm_persistent<<<NBT * 16, 256, SMEM_P>>>(h0, c0);
    out_proj<<<dim3(SEQL, 32), 272>>>(Wlin, blin, out);
}

// round 9
// speedup vs baseline: 9.4345x; 1.1074x over previous
#include <cuda_runtime.h>
#include <cuda_bf16.h>
#include <cstdint>
#include <math.h>

// ---------------------------------------------------------------------------
// LSTM decoder — mma.sync bf16 split hi/lo (3-pass), ldmatrix.
// R9: persistent uses 8 thin warps (m16n32), small reg footprint, no fp32 hist.
// ---------------------------------------------------------------------------

#define BATCH 512
#define SEQL  512
#define HID   256
#define MF    17
#define G4    1024
#define KIN   273
#define NBT   8
#define BT    64
#define NROWS (SEQL * BATCH)
#define KPU   132            // u32 per bf16 row (264 bf16); 528B rows, LDSM-clean

typedef unsigned long long ull;

__device__ float          g_Z[(size_t)NROWS * G4];          // 1 GB
__device__ float          g_corr[G4];
__device__ int            g_cnt[NBT];
__device__ __nv_bfloat16  g_Ahi[(size_t)NROWS * HID];
__device__ __nv_bfloat16  g_Alo[(size_t)NROWS * HID];
__device__ __nv_bfloat16  g_hh_hi[(size_t)SEQL * BATCH * HID];  // h history bf16
__device__ __nv_bfloat16  g_hh_lo[(size_t)SEQL * BATCH * HID];
__device__ __nv_bfloat16  g_Wzhi[G4 * HID], g_Wzlo[G4 * HID];   // z-proj (plain)
__device__ __nv_bfloat16  g_Wq_hi[G4 * HID], g_Wq_lo[G4 * HID]; // Whh (permuted)
__device__ __nv_bfloat16  g_Wp_hi[G4 * HID], g_Wp_lo[G4 * HID]; // Wc  (permuted)

__device__ __forceinline__ float sigm(float x) {
    return __fdividef(1.0f, 1.0f + __expf(-x));
}
__device__ __forceinline__ float tanh_e(float x) {
    return 1.0f - __fdividef(2.0f, __expf(2.0f * x) + 1.0f);
}
__device__ __forceinline__ void mma_bf16(float* d, const uint32_t* a,
                                         uint32_t b0, uint32_t b1) {
    asm volatile("mma.sync.aligned.m16n8k16.row.col.f32.bf16.bf16.f32 "
        "{%0,%1,%2,%3}, {%4,%5,%6,%7}, {%8,%9}, {%0,%1,%2,%3};"
        : "+f"(d[0]), "+f"(d[1]), "+f"(d[2]), "+f"(d[3])
        : "r"(a[0]), "r"(a[1]), "r"(a[2]), "r"(a[3]), "r"(b0), "r"(b1));
}
#define LDSM4(r0, r1, r2, r3, addr) \
    asm volatile("ldmatrix.sync.aligned.m8n8.x4.shared.b16 {%0,%1,%2,%3}, [%4];" \
        : "=r"(r0), "=r"(r1), "=r"(r2), "=r"(r3) : "r"(addr))
__device__ __forceinline__ void red_release(int* p) {
    asm volatile("red.release.gpu.global.add.s32 [%0], 1;" :: "l"(p) : "memory");
}
__device__ __forceinline__ int ld_acquire(const int* p) {
    int v;
    asm volatile("ld.acquire.gpu.global.s32 %0, [%1];" : "=r"(v) : "l"(p) : "memory");
    return v;
}
__device__ __forceinline__ uint32_t smem_u32(const void* p) {
    uint32_t a;
    asm("{ .reg .u64 t; cvta.to.shared.u64 t, %1; cvt.u32.u64 %0, t; }" : "=r"(a) : "l"(p));
    return a;
}
__device__ __forceinline__ uint32_t pack_hi(float x, float y) {
    __nv_bfloat162 v(__float2bfloat16_rn(x), __float2bfloat16_rn(y));
    return *reinterpret_cast<uint32_t*>(&v);
}
__device__ __forceinline__ uint32_t pack_lo(float x, float y) {
    float hx = __bfloat162float(__float2bfloat16_rn(x));
    float hy = __bfloat162float(__float2bfloat16_rn(y));
    __nv_bfloat162 v(__float2bfloat16_rn(x - hx), __float2bfloat16_rn(y - hy));
    return *reinterpret_cast<uint32_t*>(&v);
}

// ---------------------------------------------------------------------------
// conv_a: fp32 -> hi/lo bf16, row remap r = t*512 + b
// ---------------------------------------------------------------------------
__global__ __launch_bounds__(256)
void conv_a(const float* __restrict__ inseq) {
    size_t i  = (size_t)blockIdx.x * 256 + threadIdx.x;
    size_t e0 = i * 4;
    int r = (int)(e0 >> 8), k = (int)(e0 & 255);
    int b = r & 511, t = r >> 9;
    float4 v = *reinterpret_cast<const float4*>(inseq + ((size_t)(b * SEQL + t)) * HID + k);
    *reinterpret_cast<uint2*>(&g_Ahi[e0]) = make_uint2(pack_hi(v.x, v.y), pack_hi(v.z, v.w));
    *reinterpret_cast<uint2*>(&g_Alo[e0]) = make_uint2(pack_lo(v.x, v.y), pack_lo(v.z, v.w));
}

// ---------------------------------------------------------------------------
// setup: Wc fold, splits (plain Wz; permuted Whh/Wc), corr, counters.
// Permutation: row j=(gate,dim) -> [dt][nl], nl = (dl>>3)*32 + gate*8 + (dl&7).
// ---------------------------------------------------------------------------
__global__ void setup_fold(const float* __restrict__ Whh, const float* __restrict__ Wih,
                           const float* __restrict__ Wlin, const float* __restrict__ blin) {
    const int j = blockIdx.x, k = threadIdx.x;
    const int gate = j >> 8, dim = j & 255;
    const int dt = dim >> 4, dl = dim & 15;
    const int nl = (dl >> 3) * 32 + gate * 8 + (dl & 7);
    const size_t pidx = ((size_t)(dt * 64 + nl)) * HID + k;

    float whh = Whh[j * HID + k];
    float wc  = whh;
#pragma unroll
    for (int m = 0; m < MF; m++)
        wc += Wih[j * KIN + m] * Wlin[m * HID + k];
    float wz = Wih[j * KIN + 17 + k];

    __nv_bfloat16 h;
    h = __float2bfloat16_rn(whh);
    g_Wq_hi[pidx] = h;
    g_Wq_lo[pidx] = __float2bfloat16_rn(whh - __bfloat162float(h));
    h = __float2bfloat16_rn(wc);
    g_Wp_hi[pidx] = h;
    g_Wp_lo[pidx] = __float2bfloat16_rn(wc - __bfloat162float(h));
    h = __float2bfloat16_rn(wz);
    g_Wzhi[j * HID + k] = h;
    g_Wzlo[j * HID + k] = __float2bfloat16_rn(wz - __bfloat162float(h));

    if (k == 0) {
        float c = 0.0f;
#pragma unroll
        for (int m = 0; m < MF; m++) c += Wih[j * KIN + m] * blin[m];
        g_corr[j] = c;
    }
    if (j == 0 && k < NBT) g_cnt[k] = 0;
}

// ---------------------------------------------------------------------------
// gemm_z: 2048 CTAs x (128 rows, 1024 cols), K=256, 3-pass split. (R8 proven)
// ---------------------------------------------------------------------------
#define GZ_A_U   (128 * KPU)
#define GZ_W_OFF (2 * GZ_A_U)
#define GZ_W_U   (64 * KPU)
#define SMEM_GZ  ((2 * GZ_A_U + 2 * GZ_W_U) * 4)

__global__ __launch_bounds__(256, 1)
void gemm_z(const float* __restrict__ bih, const float* __restrict__ bhh) {
    extern __shared__ uint32_t smu[];
    const uint32_t ubase = smem_u32(smu);
    const int tid = threadIdx.x;
    const int wid = tid >> 5, l = tid & 31;
    const int g = l >> 2, c = l & 3;
    const int mt2 = wid & 3, nh = wid >> 2;
    const int R0 = blockIdx.x * 128;

    for (int idx = tid; idx < 128 * 32; idx += 256) {
        int row = idx >> 5, seg = idx & 31;
        *reinterpret_cast<uint4*>(&smu[row * KPU + seg * 4]) =
            *reinterpret_cast<const uint4*>(g_Ahi + (size_t)(R0 + row) * HID + seg * 8);
        *reinterpret_cast<uint4*>(&smu[GZ_A_U + row * KPU + seg * 4]) =
            *reinterpret_cast<const uint4*>(g_Alo + (size_t)(R0 + row) * HID + seg * 8);
    }

    uint32_t aAd[2], wBd[2];
#pragma unroll
    for (int h = 0; h < 2; h++)
        aAd[h] = ubase + (uint32_t)((mt2 * 32 + h * 16 + (l & 15)) * KPU) * 4 + (l >> 4) * 16;
#pragma unroll
    for (int p2 = 0; p2 < 2; p2++)
        wBd[p2] = ubase + (uint32_t)(GZ_W_OFF + (nh * 32 + p2 * 16 + (l >> 4) * 8 + (l & 7)) * KPU) * 4
                + ((l >> 3) & 1) * 16;

    const uint32_t ALO = (uint32_t)GZ_A_U * 4;
    const uint32_t WLO = (uint32_t)GZ_W_U * 4;

    for (int nt = 0; nt < 16; nt++) {
        __syncthreads();
        for (int idx = tid; idx < 64 * 32; idx += 256) {
            int row = idx >> 5, seg = idx & 31;
            *reinterpret_cast<uint4*>(&smu[GZ_W_OFF + row * KPU + seg * 4]) =
                *reinterpret_cast<const uint4*>(g_Wzhi + (size_t)(nt * 64 + row) * HID + seg * 8);
            *reinterpret_cast<uint4*>(&smu[GZ_W_OFF + GZ_W_U + row * KPU + seg * 4]) =
                *reinterpret_cast<const uint4*>(g_Wzlo + (size_t)(nt * 64 + row) * HID + seg * 8);
        }
        __syncthreads();

        float d[2][4][4];
#pragma unroll
        for (int h = 0; h < 2; h++)
#pragma unroll
            for (int n8 = 0; n8 < 4; n8++)
#pragma unroll
                for (int q = 0; q < 4; q++) d[h][n8][q] = 0.0f;

        for (int p = 0; p < 3; p++) {
            const uint32_t aoff = (p == 2) ? ALO : 0u;
            const uint32_t boff = (p == 1) ? WLO : 0u;
#pragma unroll
            for (int ks = 0; ks < 16; ks++) {
                const uint32_t kb = ks * 32;
                uint32_t u0, u1, u2, u3, v0, v1, v2, v3, a0[4], a1[4];
                LDSM4(a0[0], a0[1], a0[2], a0[3], aAd[0] + aoff + kb);
                LDSM4(a1[0], a1[1], a1[2], a1[3], aAd[1] + aoff + kb);
                LDSM4(u0, u1, u2, u3, wBd[0] + boff + kb);
                LDSM4(v0, v1, v2, v3, wBd[1] + boff + kb);
                mma_bf16(d[0][0], a0, u0, u1); mma_bf16(d[0][1], a0, u2, u3);
                mma_bf16(d[0][2], a0, v0, v1); mma_bf16(d[0][3], a0, v2, v3);
                mma_bf16(d[1][0], a1, u0, u1); mma_bf16(d[1][1], a1, u2, u3);
                mma_bf16(d[1][2], a1, v0, v1); mma_bf16(d[1][3], a1, v2, v3);
            }
        }

#pragma unroll
        for (int h = 0; h < 2; h++)
#pragma unroll
            for (int n8 = 0; n8 < 4; n8++) {
                int col = nt * 64 + nh * 32 + n8 * 8 + 2 * c;
                float bs0 = __ldg(bih + col) + __ldg(bhh + col);
                float bs1 = __ldg(bih + col + 1) + __ldg(bhh + col + 1);
                int r0 = R0 + mt2 * 32 + h * 16 + g;
                *reinterpret_cast<float2*>(g_Z + (size_t)r0 * G4 + col) =
                    make_float2(d[h][n8][0] + bs0, d[h][n8][1] + bs1);
                *reinterpret_cast<float2*>(g_Z + (size_t)(r0 + 8) * G4 + col) =
                    make_float2(d[h][n8][2] + bs0, d[h][n8][3] + bs1);
            }
    }
}

// ---------------------------------------------------------------------------
// persistent: 128 CTAs (8 bt x 16 dt), 256 threads, 8 warps EACH m16n32.
// warp: mt = wid&3 (rows mt*16..+16), nt = wid>>2 (cols nt*32..+32 permuted).
// Thread state: 2 rows x 2 dims; d quads = gate quads. No fp32 hist.
// ---------------------------------------------------------------------------
#define P_BUF_U (64 * KPU)
#define P_X_OFF (2 * P_BUF_U)
#define SMEM_P  (4 * P_BUF_U * 4)

__global__ __launch_bounds__(256, 1)
void lstm_persistent(const float* __restrict__ h0, const float* __restrict__ c0) {
    extern __shared__ uint32_t smu[];
    const uint32_t ubase = smem_u32(smu);
    const int tid = threadIdx.x;
    const int wid = tid >> 5, l = tid & 31;
    const int g = l >> 2, c = l & 3;
    const int mt = wid & 3, nt = wid >> 2;
    const int bt = blockIdx.x >> 4, dt = blockIdx.x & 15;
    const int bb0 = bt * BT, d0 = dt * 16;
    const int dl0 = nt * 8 + 2 * c;

    // ldmatrix lane addresses
    const uint32_t aXd = ubase
        + (uint32_t)(P_X_OFF + (mt * 16 + (l & 15)) * KPU) * 4 + (l >> 4) * 16;
    uint32_t wBd[2];
#pragma unroll
    for (int p2 = 0; p2 < 2; p2++)
        wBd[p2] = ubase
            + (uint32_t)((nt * 32 + p2 * 16 + (l >> 4) * 8 + (l & 7)) * KPU) * 4
            + ((l >> 3) & 1) * 16;
    const uint32_t LOFF = (uint32_t)P_BUF_U * 4;

    // per-thread state: rows mt*16 + rh*8 + g (rh=0,1), dims d0+dl0, d0+dl0+1
    float2 cst[2], cr[4];
#pragma unroll
    for (int rh = 0; rh < 2; rh++)
        cst[rh] = *reinterpret_cast<const float2*>(
            c0 + (size_t)(bb0 + mt * 16 + rh * 8 + g) * HID + d0 + dl0);
#pragma unroll
    for (int ga = 0; ga < 4; ga++)
        cr[ga] = *reinterpret_cast<const float2*>(g_corr + ga * HID + d0 + dl0);

    // stage permuted W_hh (step 0)
    for (int idx = tid; idx < 64 * 32; idx += 256) {
        int row = idx >> 5, seg = idx & 31;
        size_t src = (size_t)(dt * 64 + row) * HID + seg * 8;
        *reinterpret_cast<uint4*>(&smu[row * KPU + seg * 4]) =
            *reinterpret_cast<const uint4*>(g_Wq_hi + src);
        *reinterpret_cast<uint4*>(&smu[P_BUF_U + row * KPU + seg * 4]) =
            *reinterpret_cast<const uint4*>(g_Wq_lo + src);
    }

    for (int t = 0; t < SEQL; t++) {
        // Z prefetch (h-independent, issued before the spin)
        float2 zz[2][4];
#pragma unroll
        for (int rh = 0; rh < 2; rh++) {
            const float* zb = g_Z
                + ((size_t)t * BATCH + bb0 + mt * 16 + rh * 8 + g) * G4 + d0 + dl0;
#pragma unroll
            for (int ga = 0; ga < 4; ga++)
                zz[rh][ga] = __ldcg(reinterpret_cast<const float2*>(zb + ga * HID));
        }

        if (t > 0) {
            if (tid == 0) {
                const int target = 16 * t;
                while (ld_acquire(&g_cnt[bt]) < target) { }
            }
            __syncthreads();
        }

        // stage X = h_{t-1}
        if (t == 0) {
            const float* src = h0 + (size_t)bb0 * HID;
            for (int idx = tid; idx < 64 * 64; idx += 256) {
                int row = idx >> 6, seg = idx & 63;
                float4 v = *reinterpret_cast<const float4*>(src + row * HID + seg * 4);
                int base = P_X_OFF + row * KPU + seg * 2;
                *reinterpret_cast<uint2*>(&smu[base]) =
                    make_uint2(pack_hi(v.x, v.y), pack_hi(v.z, v.w));
                *reinterpret_cast<uint2*>(&smu[base + P_BUF_U]) =
                    make_uint2(pack_lo(v.x, v.y), pack_lo(v.z, v.w));
            }
        } else {
            const uint4* sH = reinterpret_cast<const uint4*>(
                g_hh_hi + ((size_t)(t - 1) * BATCH + bb0) * HID);
            const uint4* sL = reinterpret_cast<const uint4*>(
                g_hh_lo + ((size_t)(t - 1) * BATCH + bb0) * HID);
            for (int idx = tid; idx < 64 * 32; idx += 256) {
                int row = idx >> 5, seg = idx & 31;
                *reinterpret_cast<uint4*>(&smu[P_X_OFF + row * KPU + seg * 4]) = sH[idx];
                *reinterpret_cast<uint4*>(&smu[P_X_OFF + P_BUF_U + row * KPU + seg * 4]) = sL[idx];
            }
        }
        __syncthreads();

        // GEMM m16n32, K=256, 3-pass split
        float d[4][4];
#pragma unroll
        for (int n8 = 0; n8 < 4; n8++)
#pragma unroll
            for (int q = 0; q < 4; q++) d[n8][q] = 0.0f;

        for (int p = 0; p < 3; p++) {
            const uint32_t aoff = (p == 2) ? LOFF : 0u;
            const uint32_t boff = (p == 1) ? LOFF : 0u;
#pragma unroll
            for (int ks = 0; ks < 16; ks++) {
                const uint32_t kb = ks * 32;
                uint32_t u0, u1, u2, u3, v0, v1, v2, v3, a0[4];
                LDSM4(a0[0], a0[1], a0[2], a0[3], aXd + aoff + kb);
                LDSM4(u0, u1, u2, u3, wBd[0] + boff + kb);
                LDSM4(v0, v1, v2, v3, wBd[1] + boff + kb);
                mma_bf16(d[0], a0, u0, u1); mma_bf16(d[1], a0, u2, u3);
                mma_bf16(d[2], a0, v0, v1); mma_bf16(d[3], a0, v2, v3);
            }
        }

        // register-resident epilogue: d[gate][rh*2+j], j = dim pair element
#pragma unroll
        for (int rh = 0; rh < 2; rh++) {
            int row = mt * 16 + rh * 8 + g;
            float* cs = &cst[rh].x;
            float hv[2];
#pragma unroll
            for (int j = 0; j < 2; j++) {
                int q = rh * 2 + j;
                float iv = d[0][q] + (&zz[rh][0].x)[j];
                float fv = d[1][q] + (&zz[rh][1].x)[j];
                float gv = d[2][q] + (&zz[rh][2].x)[j];
                float ov = d[3][q] + (&zz[rh][3].x)[j];
                if (t > 0) {
                    iv += (&cr[0].x)[j]; fv += (&cr[1].x)[j];
                    gv += (&cr[2].x)[j]; ov += (&cr[3].x)[j];
                }
                float cn = sigm(fv) * cs[j] + sigm(iv) * tanh_e(gv);
                cs[j] = cn;
                hv[j] = sigm(ov) * tanh_e(cn);
            }
            size_t base = ((size_t)t * BATCH + bb0 + row) * HID + d0 + dl0;
            reinterpret_cast<uint32_t*>(g_hh_hi)[base >> 1] = pack_hi(hv[0], hv[1]);
            reinterpret_cast<uint32_t*>(g_hh_lo)[base >> 1] = pack_lo(hv[0], hv[1]);
        }
        __syncthreads();
        if (tid == 0) red_release(&g_cnt[bt]);

        // swap folded weights in after step 0
        if (t == 0) {
            for (int idx = tid; idx < 64 * 32; idx += 256) {
                int row = idx >> 5, seg = idx & 31;
                size_t src = (size_t)(dt * 64 + row) * HID + seg * 8;
                *reinterpret_cast<uint4*>(&smu[row * KPU + seg * 4]) =
                    *reinterpret_cast<const uint4*>(g_Wp_hi + src);
                *reinterpret_cast<uint4*>(&smu[P_BUF_U + row * KPU + seg * 4]) =
                    *reinterpret_cast<const uint4*>(g_Wp_lo + src);
            }
        }
    }
}

// ---------------------------------------------------------------------------
// out_proj: h reconstructed = hi + lo; out[b][t][m] = h . W_lin[m] + b_lin[m]
// ---------------------------------------------------------------------------
__global__ void out_proj(const float* __restrict__ Wlin, const float* __restrict__ blin,
                         float* __restrict__ out) {
    __shared__ float hs[16 * HID];
    const int t  = blockIdx.x;
    const int b0 = blockIdx.y * 16;
    const size_t base = ((size_t)t * BATCH + b0) * HID;
    const uint32_t* sH = reinterpret_cast<const uint32_t*>(g_hh_hi + base);
    const uint32_t* sL = reinterpret_cast<const uint32_t*>(g_hh_lo + base);
    for (int idx = threadIdx.x; idx < 16 * HID / 2; idx += 272) {
        uint32_t uh = sH[idx], ul = sL[idx];
        __nv_bfloat162 vh = *reinterpret_cast<__nv_bfloat162*>(&uh);
        __nv_bfloat162 vl = *reinterpret_cast<__nv_bfloat162*>(&ul);
        hs[2 * idx]     = __bfloat162float(vh.x) + __bfloat162float(vl.x);
        hs[2 * idx + 1] = __bfloat162float(vh.y) + __bfloat162float(vl.y);
    }
    __syncthreads();

    const int bl = threadIdx.x / MF;
    const int m  = threadIdx.x - bl * MF;
    const float* xr = hs + bl * HID;
    const float* wl = Wlin + m * HID;
    float s0 = 0, s1 = 0, s2 = 0, s3 = 0;
#pragma unroll 8
    for (int k = 0; k < HID; k += 4) {
        s0 += xr[k] * wl[k];         s1 += xr[k + 1] * wl[k + 1];
        s2 += xr[k + 2] * wl[k + 2]; s3 += xr[k + 3] * wl[k + 3];
    }
    out[((size_t)(b0 + bl) * SEQL + t) * MF + m] = blin[m] + s0 + s1 + s2 + s3;
}

// ---------------------------------------------------------------------------
extern "C" void kernel_launch(void* const* d_in, const int* in_sizes, int n_in,
                              void* d_out, int out_size) {
    const float* inseq = (const float*)d_in[0];
    const float* h0    = (const float*)d_in[1];
    const float* c0    = (const float*)d_in[2];
    const float* Wih   = (const float*)d_in[3];
    const float* Whh   = (const float*)d_in[4];
    const float* bih   = (const float*)d_in[5];
    const float* bhh   = (const float*)d_in[6];
    const float* Wlin  = (const float*)d_in[7];
    const float* blin  = (const float*)d_in[8];
    float* out = (float*)d_out;

    cudaFuncSetAttribute(gemm_z, cudaFuncAttributeMaxDynamicSharedMemorySize, SMEM_GZ);
    cudaFuncSetAttribute(lstm_persistent, cudaFuncAttributeMaxDynamicSharedMemorySize, SMEM_P);

    setup_fold<<<G4, HID>>>(Whh, Wih, Wlin, blin);
    conv_a<<<65536, 256>>>(inseq);
    gemm_z<<<2048, 256, SMEM_GZ>>>(bih, bhh);
    lstm_persistent<<<NBT * 16, 256, SMEM_P>>>(h0, c0);
    out_proj<<<dim3(SEQL, 32), 272>>>(Wlin, blin, out);
}

// round 10
// speedup vs baseline: 9.5438x; 1.0116x over previous
#include <cuda_runtime.h>
#include <cuda_bf16.h>
#include <cstdint>
#include <math.h>

// ---------------------------------------------------------------------------
// LSTM decoder — mma.sync bf16 split hi/lo (3-pass), ldmatrix, cp.async.
// R10: cp.async staging everywhere, smem Z double-buffer, per-warp release,
//      gemm_z W double-buffering.
// ---------------------------------------------------------------------------

#define BATCH 512
#define SEQL  512
#define HID   256
#define MF    17
#define G4    1024
#define KIN   273
#define NBT   8
#define BT    64
#define NROWS (SEQL * BATCH)
#define KPU   132            // u32 per bf16 row (264 bf16); 528B rows, LDSM-clean

typedef unsigned long long ull;

__device__ float          g_Z[(size_t)NROWS * G4];          // 1 GB
__device__ float          g_corr[G4];
__device__ int            g_cnt[NBT];
__device__ __nv_bfloat16  g_Ahi[(size_t)NROWS * HID];
__device__ __nv_bfloat16  g_Alo[(size_t)NROWS * HID];
__device__ __nv_bfloat16  g_hh_hi[(size_t)SEQL * BATCH * HID];
__device__ __nv_bfloat16  g_hh_lo[(size_t)SEQL * BATCH * HID];
__device__ __nv_bfloat16  g_Wzhi[G4 * HID], g_Wzlo[G4 * HID];   // z-proj (plain)
__device__ __nv_bfloat16  g_Wq_hi[G4 * HID], g_Wq_lo[G4 * HID]; // Whh (permuted)
__device__ __nv_bfloat16  g_Wp_hi[G4 * HID], g_Wp_lo[G4 * HID]; // Wc  (permuted)

__device__ __forceinline__ float sigm(float x) {
    return __fdividef(1.0f, 1.0f + __expf(-x));
}
__device__ __forceinline__ float tanh_e(float x) {
    return 1.0f - __fdividef(2.0f, __expf(2.0f * x) + 1.0f);
}
__device__ __forceinline__ void mma_bf16(float* d, const uint32_t* a,
                                         uint32_t b0, uint32_t b1) {
    asm volatile("mma.sync.aligned.m16n8k16.row.col.f32.bf16.bf16.f32 "
        "{%0,%1,%2,%3}, {%4,%5,%6,%7}, {%8,%9}, {%0,%1,%2,%3};"
        : "+f"(d[0]), "+f"(d[1]), "+f"(d[2]), "+f"(d[3])
        : "r"(a[0]), "r"(a[1]), "r"(a[2]), "r"(a[3]), "r"(b0), "r"(b1));
}
#define LDSM4(r0, r1, r2, r3, addr) \
    asm volatile("ldmatrix.sync.aligned.m8n8.x4.shared.b16 {%0,%1,%2,%3}, [%4];" \
        : "=r"(r0), "=r"(r1), "=r"(r2), "=r"(r3) : "r"(addr))
__device__ __forceinline__ void cp16(uint32_t sdst, const void* gsrc) {
    asm volatile("cp.async.cg.shared.global [%0], [%1], 16;"
                 :: "r"(sdst), "l"(gsrc) : "memory");
}
#define CP_COMMIT()  asm volatile("cp.async.commit_group;" ::: "memory")
#define CP_WAIT(n)   asm volatile("cp.async.wait_group %0;" :: "n"(n) : "memory")
__device__ __forceinline__ void red_release(int* p) {
    asm volatile("red.release.gpu.global.add.s32 [%0], 1;" :: "l"(p) : "memory");
}
__device__ __forceinline__ int ld_acquire(const int* p) {
    int v;
    asm volatile("ld.acquire.gpu.global.s32 %0, [%1];" : "=r"(v) : "l"(p) : "memory");
    return v;
}
__device__ __forceinline__ uint32_t smem_u32(const void* p) {
    uint32_t a;
    asm("{ .reg .u64 t; cvta.to.shared.u64 t, %1; cvt.u32.u64 %0, t; }" : "=r"(a) : "l"(p));
    return a;
}
__device__ __forceinline__ uint32_t pack_hi(float x, float y) {
    __nv_bfloat162 v(__float2bfloat16_rn(x), __float2bfloat16_rn(y));
    return *reinterpret_cast<uint32_t*>(&v);
}
__device__ __forceinline__ uint32_t pack_lo(float x, float y) {
    float hx = __bfloat162float(__float2bfloat16_rn(x));
    float hy = __bfloat162float(__float2bfloat16_rn(y));
    __nv_bfloat162 v(__float2bfloat16_rn(x - hx), __float2bfloat16_rn(y - hy));
    return *reinterpret_cast<uint32_t*>(&v);
}

// ---------------------------------------------------------------------------
// conv_a: fp32 -> hi/lo bf16, row remap r = t*512 + b
// ---------------------------------------------------------------------------
__global__ __launch_bounds__(256)
void conv_a(const float* __restrict__ inseq) {
    size_t i  = (size_t)blockIdx.x * 256 + threadIdx.x;
    size_t e0 = i * 4;
    int r = (int)(e0 >> 8), k = (int)(e0 & 255);
    int b = r & 511, t = r >> 9;
    float4 v = *reinterpret_cast<const float4*>(inseq + ((size_t)(b * SEQL + t)) * HID + k);
    *reinterpret_cast<uint2*>(&g_Ahi[e0]) = make_uint2(pack_hi(v.x, v.y), pack_hi(v.z, v.w));
    *reinterpret_cast<uint2*>(&g_Alo[e0]) = make_uint2(pack_lo(v.x, v.y), pack_lo(v.z, v.w));
}

// ---------------------------------------------------------------------------
// setup: Wc fold, splits (plain Wz; permuted Whh/Wc), corr, counters.
// ---------------------------------------------------------------------------
__global__ void setup_fold(const float* __restrict__ Whh, const float* __restrict__ Wih,
                           const float* __restrict__ Wlin, const float* __restrict__ blin) {
    const int j = blockIdx.x, k = threadIdx.x;
    const int gate = j >> 8, dim = j & 255;
    const int dt = dim >> 4, dl = dim & 15;
    const int nl = (dl >> 3) * 32 + gate * 8 + (dl & 7);
    const size_t pidx = ((size_t)(dt * 64 + nl)) * HID + k;

    float whh = Whh[j * HID + k];
    float wc  = whh;
#pragma unroll
    for (int m = 0; m < MF; m++)
        wc += Wih[j * KIN + m] * Wlin[m * HID + k];
    float wz = Wih[j * KIN + 17 + k];

    __nv_bfloat16 h;
    h = __float2bfloat16_rn(whh);
    g_Wq_hi[pidx] = h;
    g_Wq_lo[pidx] = __float2bfloat16_rn(whh - __bfloat162float(h));
    h = __float2bfloat16_rn(wc);
    g_Wp_hi[pidx] = h;
    g_Wp_lo[pidx] = __float2bfloat16_rn(wc - __bfloat162float(h));
    h = __float2bfloat16_rn(wz);
    g_Wzhi[j * HID + k] = h;
    g_Wzlo[j * HID + k] = __float2bfloat16_rn(wz - __bfloat162float(h));

    if (k == 0) {
        float c = 0.0f;
#pragma unroll
        for (int m = 0; m < MF; m++) c += Wih[j * KIN + m] * blin[m];
        g_corr[j] = c;
    }
    if (j == 0 && k < NBT) g_cnt[k] = 0;
}

// ---------------------------------------------------------------------------
// gemm_z: 4096 CTAs x (64 rows, 1024 cols), K=256, 3-pass split.
// A resident (hi+lo), W tiles (64 cols) DOUBLE-BUFFERED via cp.async.
// 8 warps m16n32: mt = wid&3, nh = wid>>2.
// ---------------------------------------------------------------------------
#define GZ_A_U   (64 * KPU)                 // 8448 u32 per A buffer
#define GZ_W_OFF (2 * GZ_A_U)
#define GZ_WT_U  (64 * KPU)                 // one W tile (hi or lo)
#define SMEM_GZ  ((2 * GZ_A_U + 4 * GZ_WT_U) * 4)   // 202752 B

__global__ __launch_bounds__(256, 1)
void gemm_z(const float* __restrict__ bih, const float* __restrict__ bhh) {
    extern __shared__ uint32_t smu[];
    const uint32_t ubase = smem_u32(smu);
    const int tid = threadIdx.x;
    const int wid = tid >> 5, l = tid & 31;
    const int g = l >> 2, c = l & 3;
    const int mt = wid & 3, nh = wid >> 2;
    const int R0 = blockIdx.x * 64;

    // prologue: A hi/lo + W tile 0 via cp.async (one group)
    for (int idx = tid; idx < 64 * 32 * 2; idx += 256) {
        int sel = idx >> 11, r2 = (idx >> 5) & 63, seg = idx & 31;
        const __nv_bfloat16* src = sel ? g_Alo : g_Ahi;
        cp16(ubase + (uint32_t)(sel * GZ_A_U + r2 * KPU + seg * 4) * 4,
             src + (size_t)(R0 + r2) * HID + seg * 8);
    }
    for (int idx = tid; idx < 64 * 32 * 2; idx += 256) {
        int sel = idx >> 11, r2 = (idx >> 5) & 63, seg = idx & 31;
        const __nv_bfloat16* src = sel ? g_Wzlo : g_Wzhi;
        cp16(ubase + (uint32_t)(GZ_W_OFF + sel * GZ_WT_U + r2 * KPU + seg * 4) * 4,
             src + (size_t)r2 * HID + seg * 8);
    }
    CP_COMMIT();

    // ldmatrix lane addresses
    const uint32_t aAd = ubase + (uint32_t)((mt * 16 + (l & 15)) * KPU) * 4 + (l >> 4) * 16;
    uint32_t wBd[2][2];
#pragma unroll
    for (int buf = 0; buf < 2; buf++)
#pragma unroll
        for (int p2 = 0; p2 < 2; p2++)
            wBd[buf][p2] = ubase
                + (uint32_t)(GZ_W_OFF + buf * 2 * GZ_WT_U
                             + (nh * 32 + p2 * 16 + (l >> 4) * 8 + (l & 7)) * KPU) * 4
                + ((l >> 3) & 1) * 16;
    const uint32_t ALO = (uint32_t)GZ_A_U * 4;
    const uint32_t WLO = (uint32_t)GZ_WT_U * 4;

    for (int nt = 0; nt < 16; nt++) {
        if (nt < 15) {     // prefetch next W tile into other buffer
            int buf = (nt + 1) & 1;
            for (int idx = tid; idx < 64 * 32 * 2; idx += 256) {
                int sel = idx >> 11, r2 = (idx >> 5) & 63, seg = idx & 31;
                const __nv_bfloat16* src = sel ? g_Wzlo : g_Wzhi;
                cp16(ubase + (uint32_t)(GZ_W_OFF + (buf * 2 + sel) * GZ_WT_U
                                        + r2 * KPU + seg * 4) * 4,
                     src + (size_t)((nt + 1) * 64 + r2) * HID + seg * 8);
            }
            CP_COMMIT();
            CP_WAIT(1);
        } else {
            CP_WAIT(0);
        }
        __syncthreads();

        const int buf = nt & 1;
        float d[4][4];
#pragma unroll
        for (int n8 = 0; n8 < 4; n8++)
#pragma unroll
            for (int q = 0; q < 4; q++) d[n8][q] = 0.0f;

        for (int p = 0; p < 3; p++) {
            const uint32_t aoff = (p == 2) ? ALO : 0u;
            const uint32_t boff = (p == 1) ? WLO : 0u;
#pragma unroll
            for (int ks = 0; ks < 16; ks++) {
                const uint32_t kb = ks * 32;
                uint32_t u0, u1, u2, u3, v0, v1, v2, v3, a0[4];
                LDSM4(a0[0], a0[1], a0[2], a0[3], aAd + aoff + kb);
                LDSM4(u0, u1, u2, u3, wBd[buf][0] + boff + kb);
                LDSM4(v0, v1, v2, v3, wBd[buf][1] + boff + kb);
                mma_bf16(d[0], a0, u0, u1); mma_bf16(d[1], a0, u2, u3);
                mma_bf16(d[2], a0, v0, v1); mma_bf16(d[3], a0, v2, v3);
            }
        }

#pragma unroll
        for (int n8 = 0; n8 < 4; n8++) {
            int col = nt * 64 + nh * 32 + n8 * 8 + 2 * c;
            float bs0 = __ldg(bih + col) + __ldg(bhh + col);
            float bs1 = __ldg(bih + col + 1) + __ldg(bhh + col + 1);
            int r0 = R0 + mt * 16 + g;
            *reinterpret_cast<float2*>(g_Z + (size_t)r0 * G4 + col) =
                make_float2(d[n8][0] + bs0, d[n8][1] + bs1);
            *reinterpret_cast<float2*>(g_Z + (size_t)(r0 + 8) * G4 + col) =
                make_float2(d[n8][2] + bs0, d[n8][3] + bs1);
        }
        __syncthreads();
    }
}

// ---------------------------------------------------------------------------
// persistent: 128 CTAs (8 bt x 16 dt), 256 threads, 8 warps m16n32.
// cp.async staging; Z double-buffered in smem; per-warp release (128/step/grp).
// ---------------------------------------------------------------------------
#define P_BUF_U (64 * KPU)
#define P_X_OFF (2 * P_BUF_U)
#define SZ_OFF  (4 * P_BUF_U)
#define SZ_U    (64 * 68)                   // one Z buffer (floats == u32)
#define SMEM_P  ((4 * P_BUF_U + 2 * SZ_U) * 4)

__global__ __launch_bounds__(256, 1)
void lstm_persistent(const float* __restrict__ h0, const float* __restrict__ c0) {
    extern __shared__ uint32_t smu[];
    const uint32_t ubase = smem_u32(smu);
    const int tid = threadIdx.x;
    const int wid = tid >> 5, l = tid & 31;
    const int g = l >> 2, c = l & 3;
    const int mt = wid & 3, nt = wid >> 2;
    const int bt = blockIdx.x >> 4, dt = blockIdx.x & 15;
    const int bb0 = bt * BT, d0 = dt * 16;
    const int dl0 = nt * 8 + 2 * c;

    const uint32_t aXd = ubase
        + (uint32_t)(P_X_OFF + (mt * 16 + (l & 15)) * KPU) * 4 + (l >> 4) * 16;
    uint32_t wBd[2];
#pragma unroll
    for (int p2 = 0; p2 < 2; p2++)
        wBd[p2] = ubase
            + (uint32_t)((nt * 32 + p2 * 16 + (l >> 4) * 8 + (l & 7)) * KPU) * 4
            + ((l >> 3) & 1) * 16;
    const uint32_t LOFF = (uint32_t)P_BUF_U * 4;

    float2 cst[2], cr[4];
#pragma unroll
    for (int rh = 0; rh < 2; rh++)
        cst[rh] = *reinterpret_cast<const float2*>(
            c0 + (size_t)(bb0 + mt * 16 + rh * 8 + g) * HID + d0 + dl0);
#pragma unroll
    for (int ga = 0; ga < 4; ga++)
        cr[ga] = *reinterpret_cast<const float2*>(g_corr + ga * HID + d0 + dl0);

    // stage permuted W_hh (step 0)
    for (int idx = tid; idx < 64 * 32; idx += 256) {
        int row = idx >> 5, seg = idx & 31;
        size_t src = (size_t)(dt * 64 + row) * HID + seg * 8;
        *reinterpret_cast<uint4*>(&smu[row * KPU + seg * 4]) =
            *reinterpret_cast<const uint4*>(g_Wq_hi + src);
        *reinterpret_cast<uint4*>(&smu[P_BUF_U + row * KPU + seg * 4]) =
            *reinterpret_cast<const uint4*>(g_Wq_lo + src);
    }

    for (int t = 0; t < SEQL; t++) {
        // Z prefetch into smem (double-buffered) via cp.async, BEFORE the spin
        {
            const int zb = SZ_OFF + (t & 1) * SZ_U;
            const float* zsrc = g_Z + ((size_t)t * BATCH + bb0) * G4 + d0;
            for (int idx = tid; idx < 1024; idx += 256) {
                int row = idx >> 4, gate = (idx >> 2) & 3, j = idx & 3;
                cp16(ubase + (uint32_t)(zb + row * 68 + gate * 16 + j * 4) * 4,
                     zsrc + (size_t)row * G4 + gate * HID + j * 4);
            }
            CP_COMMIT();
        }

        if (t > 0) {
            if (tid == 0) {
                const int target = 128 * t;
                while (ld_acquire(&g_cnt[bt]) < target) { }
            }
            __syncthreads();
        }

        // stage X = h_{t-1}
        if (t == 0) {
            const float* src = h0 + (size_t)bb0 * HID;
            for (int idx = tid; idx < 64 * 64; idx += 256) {
                int row = idx >> 6, seg = idx & 63;
                float4 v = *reinterpret_cast<const float4*>(src + row * HID + seg * 4);
                int base = P_X_OFF + row * KPU + seg * 2;
                *reinterpret_cast<uint2*>(&smu[base]) =
                    make_uint2(pack_hi(v.x, v.y), pack_hi(v.z, v.w));
                *reinterpret_cast<uint2*>(&smu[base + P_BUF_U]) =
                    make_uint2(pack_lo(v.x, v.y), pack_lo(v.z, v.w));
            }
        } else {
            const size_t hb = ((size_t)(t - 1) * BATCH + bb0) * HID;
            for (int idx = tid; idx < 64 * 32 * 2; idx += 256) {
                int sel = idx >> 11, row = (idx >> 5) & 63, seg = idx & 31;
                const __nv_bfloat16* src = sel ? g_hh_lo : g_hh_hi;
                cp16(ubase + (uint32_t)(P_X_OFF + sel * P_BUF_U + row * KPU + seg * 4) * 4,
                     src + hb + (size_t)row * HID + seg * 8);
            }
            CP_COMMIT();
        }
        CP_WAIT(0);
        __syncthreads();

        // GEMM m16n32, K=256, 3-pass split
        float d[4][4];
#pragma unroll
        for (int n8 = 0; n8 < 4; n8++)
#pragma unroll
            for (int q = 0; q < 4; q++) d[n8][q] = 0.0f;

        for (int p = 0; p < 3; p++) {
            const uint32_t aoff = (p == 2) ? LOFF : 0u;
            const uint32_t boff = (p == 1) ? LOFF : 0u;
#pragma unroll
            for (int ks = 0; ks < 16; ks++) {
                const uint32_t kb = ks * 32;
                uint32_t u0, u1, u2, u3, v0, v1, v2, v3, a0[4];
                LDSM4(a0[0], a0[1], a0[2], a0[3], aXd + aoff + kb);
                LDSM4(u0, u1, u2, u3, wBd[0] + boff + kb);
                LDSM4(v0, v1, v2, v3, wBd[1] + boff + kb);
                mma_bf16(d[0], a0, u0, u1); mma_bf16(d[1], a0, u2, u3);
                mma_bf16(d[2], a0, v0, v1); mma_bf16(d[3], a0, v2, v3);
            }
        }

        // register-resident epilogue; Z from smem
        {
            const float* sZf = reinterpret_cast<const float*>(
                smu + SZ_OFF + (t & 1) * SZ_U);
#pragma unroll
            for (int rh = 0; rh < 2; rh++) {
                int row = mt * 16 + rh * 8 + g;
                float* cs = &cst[rh].x;
                float hv[2];
#pragma unroll
                for (int j = 0; j < 2; j++) {
                    int q = rh * 2 + j;
                    float iv = d[0][q] + sZf[row * 68 + 0 * 16 + dl0 + j];
                    float fv = d[1][q] + sZf[row * 68 + 1 * 16 + dl0 + j];
                    float gv = d[2][q] + sZf[row * 68 + 2 * 16 + dl0 + j];
                    float ov = d[3][q] + sZf[row * 68 + 3 * 16 + dl0 + j];
                    if (t > 0) {
                        iv += (&cr[0].x)[j]; fv += (&cr[1].x)[j];
                        gv += (&cr[2].x)[j]; ov += (&cr[3].x)[j];
                    }
                    float cn = sigm(fv) * cs[j] + sigm(iv) * tanh_e(gv);
                    cs[j] = cn;
                    hv[j] = sigm(ov) * tanh_e(cn);
                }
                size_t base = ((size_t)t * BATCH + bb0 + row) * HID + d0 + dl0;
                reinterpret_cast<uint32_t*>(g_hh_hi)[base >> 1] = pack_hi(hv[0], hv[1]);
                reinterpret_cast<uint32_t*>(g_hh_lo)[base >> 1] = pack_lo(hv[0], hv[1]);
            }
        }
        __syncwarp();
        if (l == 0) red_release(&g_cnt[bt]);   // per-warp release: 8/CTA, 128/group

        // swap folded weights in after step 0 (needs all warps past GEMM)
        if (t == 0) {
            __syncthreads();
            for (int idx = tid; idx < 64 * 32; idx += 256) {
                int row = idx >> 5, seg = idx & 31;
                size_t src = (size_t)(dt * 64 + row) * HID + seg * 8;
                *reinterpret_cast<uint4*>(&smu[row * KPU + seg * 4]) =
                    *reinterpret_cast<const uint4*>(g_Wp_hi + src);
                *reinterpret_cast<uint4*>(&smu[P_BUF_U + row * KPU + seg * 4]) =
                    *reinterpret_cast<const uint4*>(g_Wp_lo + src);
            }
        }
    }
}

// ---------------------------------------------------------------------------
// out_proj: h reconstructed = hi + lo
// ---------------------------------------------------------------------------
__global__ void out_proj(const float* __restrict__ Wlin, const float* __restrict__ blin,
                         float* __restrict__ out) {
    __shared__ float hs[16 * HID];
    const int t  = blockIdx.x;
    const int b0 = blockIdx.y * 16;
    const size_t base = ((size_t)t * BATCH + b0) * HID;
    const uint32_t* sH = reinterpret_cast<const uint32_t*>(g_hh_hi + base);
    const uint32_t* sL = reinterpret_cast<const uint32_t*>(g_hh_lo + base);
    for (int idx = threadIdx.x; idx < 16 * HID / 2; idx += 272) {
        uint32_t uh = sH[idx], ul = sL[idx];
        __nv_bfloat162 vh = *reinterpret_cast<__nv_bfloat162*>(&uh);
        __nv_bfloat162 vl = *reinterpret_cast<__nv_bfloat162*>(&ul);
        hs[2 * idx]     = __bfloat162float(vh.x) + __bfloat162float(vl.x);
        hs[2 * idx + 1] = __bfloat162float(vh.y) + __bfloat162float(vl.y);
    }
    __syncthreads();

    const int bl = threadIdx.x / MF;
    const int m  = threadIdx.x - bl * MF;
    const float* xr = hs + bl * HID;
    const float* wl = Wlin + m * HID;
    float s0 = 0, s1 = 0, s2 = 0, s3 = 0;
#pragma unroll 8
    for (int k = 0; k < HID; k += 4) {
        s0 += xr[k] * wl[k];         s1 += xr[k + 1] * wl[k + 1];
        s2 += xr[k + 2] * wl[k + 2]; s3 += xr[k + 3] * wl[k + 3];
    }
    out[((size_t)(b0 + bl) * SEQL + t) * MF + m] = blin[m] + s0 + s1 + s2 + s3;
}

// ---------------------------------------------------------------------------
extern "C" void kernel_launch(void* const* d_in, const int* in_sizes, int n_in,
                              void* d_out, int out_size) {
    const float* inseq = (const float*)d_in[0];
    const float* h0    = (const float*)d_in[1];
    const float* c0    = (const float*)d_in[2];
    const float* Wih   = (const float*)d_in[3];
    const float* Whh   = (const float*)d_in[4];
    const float* bih   = (const float*)d_in[5];
    const float* bhh   = (const float*)d_in[6];
    const float* Wlin  = (const float*)d_in[7];
    const float* blin  = (const float*)d_in[8];
    float* out = (float*)d_out;

    cudaFuncSetAttribute(gemm_z, cudaFuncAttributeMaxDynamicSharedMemorySize, SMEM_GZ);
    cudaFuncSetAttribute(lstm_persistent, cudaFuncAttributeMaxDynamicSharedMemorySize, SMEM_P);

    setup_fold<<<G4, HID>>>(Whh, Wih, Wlin, blin);
    conv_a<<<65536, 256>>>(inseq);
    gemm_z<<<4096, 256, SMEM_GZ>>>(bih, bhh);
    lstm_persistent<<<NBT * 16, 256, SMEM_P>>>(h0, c0);
    out_proj<<<dim3(SEQL, 32), 272>>>(Wlin, blin, out);
}